// round 7
// baseline (speedup 1.0000x reference)
#include <cuda_runtime.h>
#include <cuda_fp16.h>

#define D 128
#define MAX_DRUG 10000
#define MAX_DIS  15000
#define MAX_E    1048576
#define KC 16            // k-chunk per smem stage (proj)
#define NB 640           // row buckets, 16 rows each (covers 10240 rows)
#define HB 512           // edge chunks (hist/scatter blocks)
#define SPLIT 8          // blocks per bucket in the edge kernel

// Projected embeddings in fp16 (fp32 math, rounded once).
__device__ __half g_Ah[MAX_DRUG * D];   // z_drug    @ W1[0:128]  + b1
__device__ __half g_Bh[MAX_DIS  * D];   // z_disease @ W1[128:256]
// Counting-sort scratch. g_cnt zero at load; re-zeroed by scatter each launch.
__device__ int  g_cnt[NB];
__device__ int  g_ptr[NB + 1];
__device__ int  g_blkhist[HB * NB];   // per-chunk histograms (overwritten)
__device__ int  g_base[HB * NB];      // per-(chunk,bucket) scatter bases
__device__ int2 g_rec[MAX_E];         // (col | r_local<<28, eid)

// ---------------------------------------------------------------------------
// K1: fused projection GEMMs + per-chunk edge-row histograms.
// Blocks [0, tiles): 128x128 projection tiles. Blocks [tiles, tiles+HB):
// contiguous-chunk histograms (chunking matches K3 exactly).
// ---------------------------------------------------------------------------
__global__ __launch_bounds__(256) void proj_hist_kernel(
    const float* __restrict__ Zd, const float* __restrict__ Zs_,
    int n_drug, int n_dis,
    const float* __restrict__ W1, const float* __restrict__ b1,
    __half* __restrict__ A, __half* __restrict__ B,
    const int* __restrict__ row, int E, int tiles, int do_hist)
{
    const int t = threadIdx.x;

    if ((int)blockIdx.x >= tiles) {                 // ---- histogram blocks
        if (!do_hist) return;
        __shared__ int hc[NB];
        const int hb = blockIdx.x - tiles;
        const int cs = (E + HB - 1) / HB;
        const int e0 = hb * cs;
        const int e1 = min(e0 + cs, E);
        for (int i = t; i < NB; i += 256) hc[i] = 0;
        __syncthreads();
        for (int e = e0 + t; e < e1; e += 256)
            atomicAdd(&hc[row[e] >> 4], 1);
        __syncthreads();
        for (int i = t; i < NB; i += 256) {
            const int v = hc[i];
            g_blkhist[hb * NB + i] = v;
            if (v) atomicAdd(&g_cnt[i], v);        // fire-and-forget RED
        }
        return;
    }

    // ---- projection blocks
    const int tiles_drug = (n_drug + 127) / 128;
    const float* Z;
    __half* out;
    int N, koff, addb;
    int tile = blockIdx.x;
    if (tile < tiles_drug) { Z = Zd;  out = A; N = n_drug; koff = 0;   addb = 1; }
    else { tile -= tiles_drug; Z = Zs_; out = B; N = n_dis; koff = 128; addb = 0; }
    const int r0 = tile * 128;

    __shared__ float Zt[KC][128];
    __shared__ float Wt[KC][128];

    const int tx = t & 15;
    const int ty = t >> 4;

    float acc[8][8];
#pragma unroll
    for (int i = 0; i < 8; i++)
#pragma unroll
        for (int j = 0; j < 8; j++) acc[i][j] = 0.f;

    for (int kc = 0; kc < D; kc += KC) {
        __syncthreads();
#pragma unroll
        for (int i = t; i < 512; i += 256) {
            int rr = i & 127;
            int k4 = i >> 7;
            float4 v = make_float4(0.f, 0.f, 0.f, 0.f);
            if (r0 + rr < N)
                v = *reinterpret_cast<const float4*>(
                        Z + (size_t)(r0 + rr) * D + kc + k4 * 4);
            Zt[k4 * 4 + 0][rr] = v.x;
            Zt[k4 * 4 + 1][rr] = v.y;
            Zt[k4 * 4 + 2][rr] = v.z;
            Zt[k4 * 4 + 3][rr] = v.w;
        }
#pragma unroll
        for (int i = t; i < 512; i += 256) {
            int kk = i >> 5;
            int c4 = i & 31;
            *reinterpret_cast<float4*>(&Wt[kk][c4 * 4]) =
                *reinterpret_cast<const float4*>(
                    W1 + (size_t)(koff + kc + kk) * D + c4 * 4);
        }
        __syncthreads();

#pragma unroll
        for (int kk = 0; kk < KC; kk++) {
            float af[8], bf[8];
            *reinterpret_cast<float4*>(af)     = *reinterpret_cast<float4*>(&Zt[kk][ty * 8]);
            *reinterpret_cast<float4*>(af + 4) = *reinterpret_cast<float4*>(&Zt[kk][ty * 8 + 4]);
            *reinterpret_cast<float4*>(bf)     = *reinterpret_cast<float4*>(&Wt[kk][tx * 8]);
            *reinterpret_cast<float4*>(bf + 4) = *reinterpret_cast<float4*>(&Wt[kk][tx * 8 + 4]);
#pragma unroll
            for (int i = 0; i < 8; i++)
#pragma unroll
                for (int j = 0; j < 8; j++)
                    acc[i][j] = fmaf(af[i], bf[j], acc[i][j]);
        }
    }

    float bias[8];
#pragma unroll
    for (int j = 0; j < 8; j++) bias[j] = addb ? b1[tx * 8 + j] : 0.f;

#pragma unroll
    for (int i = 0; i < 8; i++) {
        int r = r0 + ty * 8 + i;
        if (r < N) {
            __half2 h[4];
#pragma unroll
            for (int j = 0; j < 4; j++)
                h[j] = __floats2half2_rn(acc[i][2 * j]     + bias[2 * j],
                                         acc[i][2 * j + 1] + bias[2 * j + 1]);
            *reinterpret_cast<uint4*>(out + (size_t)r * D + tx * 8) =
                *reinterpret_cast<uint4*>(h);
        }
    }
}

// ---------------------------------------------------------------------------
// K2: merged bucket-prefix + chunk-base kernel. One block per bucket b.
// ptr[b] = sum_{i<b} cnt[i] (masked reduction, no cross-block scan), then
// an in-block scan of b's 512 chunk counts gives the scatter bases.
// ---------------------------------------------------------------------------
__global__ __launch_bounds__(256) void scanbase_kernel()
{
    const int b = blockIdx.x;
    const int t = threadIdx.x;

    __shared__ int sP[256], sT[256];
    int p = 0, tot = 0;
    for (int i = t; i < NB; i += 256) {
        const int v = g_cnt[i];
        tot += v;
        if (i < b) p += v;
    }
    sP[t] = p;
    sT[t] = tot;
    __syncthreads();
    for (int off = 128; off > 0; off >>= 1) {
        if (t < off) { sP[t] += sP[t + off]; sT[t] += sT[t + off]; }
        __syncthreads();
    }
    const int ptr_b = sP[0];
    if (t == 0) {
        g_ptr[b] = ptr_b;
        if (b == 0) g_ptr[NB] = sT[0];
    }

    // Scan this bucket's HB chunk counts (2 elems per thread).
    __shared__ int sA[HB], sB[HB];
    const int v0 = g_blkhist[t * NB + b];
    const int v1 = g_blkhist[(t + 256) * NB + b];
    sA[t] = v0;
    sA[t + 256] = v1;
    __syncthreads();

    int* src = sA;
    int* dst = sB;
#pragma unroll
    for (int off = 1; off < HB; off <<= 1) {
        int x0 = src[t];
        if (t >= off) x0 += src[t - off];
        int x1 = src[t + 256];
        if (t + 256 >= off) x1 += src[t + 256 - off];
        dst[t] = x0;
        dst[t + 256] = x1;
        __syncthreads();
        int* tmp = src; src = dst; dst = tmp;
    }
    g_base[t * NB + b]         = ptr_b + src[t] - v0;         // exclusive
    g_base[(t + 256) * NB + b] = ptr_b + src[t + 256] - v1;
}

// ---------------------------------------------------------------------------
// K3: scatter — smem atomics against precomputed bases. Also re-arms g_cnt
// (its last reader was K2).
// ---------------------------------------------------------------------------
__global__ __launch_bounds__(256) void scatter_kernel(
    const int* __restrict__ row, const int* __restrict__ col, int E)
{
    __shared__ int soff[NB];
    const int hb = blockIdx.x;
    const int t  = threadIdx.x;
    const int cs = (E + HB - 1) / HB;
    const int e0 = hb * cs;
    const int e1 = min(e0 + cs, E);

    if (t == 0)
        for (int i = hb; i < NB; i += HB) g_cnt[i] = 0;

    for (int i = t; i < NB; i += 256) soff[i] = g_base[hb * NB + i];
    __syncthreads();

    for (int e = e0 + t; e < e1; e += 256) {
        const int r = row[e];
        const int c = col[e];
        const int p = atomicAdd(&soff[r >> 4], 1);
        g_rec[p] = make_int2(c | ((r & 15) << 28), e);
    }
}

// ---------------------------------------------------------------------------
// K4: bucketed edge compute. SPLIT blocks per bucket (grid NB*SPLIT);
// each stages the bucket's 16 A-rows in smem (4KB) and processes a
// contiguous 1/SPLIT slice of the segment. 8 edges/warp as 4 pairs.
// ---------------------------------------------------------------------------
__global__ __launch_bounds__(256) void edge_sorted_kernel(
    const float* __restrict__ W2, const float* __restrict__ b2,
    float* __restrict__ out, int n_drug)
{
    __shared__ uint4 As4[16 * 16];

    const int t    = threadIdx.x;
    const int b    = blockIdx.x / SPLIT;
    const int part = blockIdx.x % SPLIT;

    {
        const uint4* A16 = reinterpret_cast<const uint4*>(g_Ah);
        const int r = b * 16 + (t >> 4);
        As4[t] = (r < n_drug) ? A16[r * 16 + (t & 15)]
                              : make_uint4(0u, 0u, 0u, 0u);
    }
    __syncthreads();

    const int s0  = g_ptr[b];
    const int len = g_ptr[b + 1] - s0;
    const int q0  = s0 + (int)(((long long)len * part) / SPLIT);
    const int q1  = s0 + (int)(((long long)len * (part + 1)) / SPLIT);
    if (q0 >= q1) return;

    const int lane = t & 31;
    const int wid  = t >> 5;
    const int j    = lane & 15;
    const int hi   = lane >> 4;

    const float4 wa = reinterpret_cast<const float4*>(W2)[j * 2];
    const float4 wb = reinterpret_cast<const float4*>(W2)[j * 2 + 1];
    const __half2 w0  = __floats2half2_rn(wa.x, wa.y);
    const __half2 w1  = __floats2half2_rn(wa.z, wa.w);
    const __half2 w2h = __floats2half2_rn(wb.x, wb.y);
    const __half2 w3  = __floats2half2_rn(wb.z, wb.w);
    const float bias = b2[0];
    const __half2 zero = __float2half2_rn(0.f);
    const uint4* __restrict__ B16 = reinterpret_cast<const uint4*>(g_Bh);
    const unsigned full = 0xffffffffu;

    auto pair_dot = [&](const uint4& a, const uint4& bv) -> float {
        __half2 h0 = __hmax2(__hadd2(*reinterpret_cast<const __half2*>(&a.x),
                                     *reinterpret_cast<const __half2*>(&bv.x)), zero);
        __half2 h1 = __hmax2(__hadd2(*reinterpret_cast<const __half2*>(&a.y),
                                     *reinterpret_cast<const __half2*>(&bv.y)), zero);
        __half2 h2 = __hmax2(__hadd2(*reinterpret_cast<const __half2*>(&a.z),
                                     *reinterpret_cast<const __half2*>(&bv.z)), zero);
        __half2 h3 = __hmax2(__hadd2(*reinterpret_cast<const __half2*>(&a.w),
                                     *reinterpret_cast<const __half2*>(&bv.w)), zero);
        __half2 acc0 = __hfma2(h1, w1, __hmul2(h0, w0));
        __half2 acc1 = __hfma2(h3, w3, __hmul2(h2, w2h));
        float2 f0 = __half22float2(acc0);
        float2 f1 = __half22float2(acc1);
        return (f0.x + f0.y) + (f1.x + f1.y);
    };

    for (int base = q0 + wid * 8; base < q1; base += 64) {
        const int n = min(8, q1 - base);

        int2 rec = make_int2(0, 0);
        if (lane < 8)
            rec = g_rec[min(base + lane, q1 - 1)];

        int rx[4], re[4];
#pragma unroll
        for (int p = 0; p < 4; p++) {
            rx[p] = __shfl_sync(full, rec.x, 2 * p + hi);
            re[p] = __shfl_sync(full, rec.y, 2 * p + hi);
        }

        uint4 av[4], bv[4];
#pragma unroll
        for (int p = 0; p < 4; p++) {
            const int c  = rx[p] & 0x0FFFFFFF;
            const int rl = ((unsigned)rx[p]) >> 28;
            av[p] = As4[rl * 16 + j];
            bv[p] = B16[(size_t)c * 16 + j];
        }

        float s[4];
#pragma unroll
        for (int p = 0; p < 4; p++) s[p] = pair_dot(av[p], bv[p]);

#pragma unroll
        for (int off = 8; off > 0; off >>= 1) {
#pragma unroll
            for (int p = 0; p < 4; p++)
                s[p] += __shfl_xor_sync(full, s[p], off);
        }

        if (j == 0) {
#pragma unroll
            for (int p = 0; p < 4; p++)
                if (2 * p + hi < n) out[re[p]] = s[p] + bias;
        }
    }
}

// ---------------------------------------------------------------------------
// Fallback flat edge kernel (round-4, known-good) for odd shapes.
// ---------------------------------------------------------------------------
__global__ __launch_bounds__(256) void edge_kernel_flat(
    const int* __restrict__ row, const int* __restrict__ col,
    const float* __restrict__ W2, const float* __restrict__ b2,
    float* __restrict__ out, int E)
{
    const int lane = threadIdx.x & 31;
    const int warp = blockIdx.x * 8 + (threadIdx.x >> 5);
    const int e0 = warp * 4;
    if (e0 >= E) return;

    const float4 w2 = reinterpret_cast<const float4*>(W2)[lane];
    const float bias = b2[0];
    const int last = E - 1;

    const int r0i = row[e0];
    const int c0i = col[e0];
    const int r1i = row[min(e0 + 1, last)];
    const int c1i = col[min(e0 + 1, last)];
    const int r2i = row[min(e0 + 2, last)];
    const int c2i = col[min(e0 + 2, last)];
    const int r3i = row[min(e0 + 3, last)];
    const int c3i = col[min(e0 + 3, last)];

    const uint2* __restrict__ Ah = reinterpret_cast<const uint2*>(g_Ah);
    const uint2* __restrict__ Bh = reinterpret_cast<const uint2*>(g_Bh);
    const uint2 a0 = Ah[(size_t)r0i * 32 + lane];
    const uint2 b0 = Bh[(size_t)c0i * 32 + lane];
    const uint2 a1 = Ah[(size_t)r1i * 32 + lane];
    const uint2 b1v = Bh[(size_t)c1i * 32 + lane];
    const uint2 a2 = Ah[(size_t)r2i * 32 + lane];
    const uint2 b2v = Bh[(size_t)c2i * 32 + lane];
    const uint2 a3 = Ah[(size_t)r3i * 32 + lane];
    const uint2 b3v = Bh[(size_t)c3i * 32 + lane];

    const __half2 zero = __float2half2_rn(0.f);
    auto edge_dot = [&](uint2 a, uint2 b) -> float {
        __half2 al = *reinterpret_cast<__half2*>(&a.x);
        __half2 ah = *reinterpret_cast<__half2*>(&a.y);
        __half2 bl = *reinterpret_cast<__half2*>(&b.x);
        __half2 bh = *reinterpret_cast<__half2*>(&b.y);
        __half2 h0 = __hmax2(__hadd2(al, bl), zero);
        __half2 h1 = __hmax2(__hadd2(ah, bh), zero);
        float2 f0 = __half22float2(h0);
        float2 f1 = __half22float2(h1);
        return f0.x * w2.x + f0.y * w2.y + f1.x * w2.z + f1.y * w2.w;
    };

    float s0 = edge_dot(a0, b0);
    float s1 = edge_dot(a1, b1v);
    float s2 = edge_dot(a2, b2v);
    float s3 = edge_dot(a3, b3v);

    const unsigned full = 0xffffffffu;
    const bool hi = (lane & 16) != 0;
    float va = hi ? s1 : s0;
    float oa = hi ? s0 : s1;
    va += __shfl_xor_sync(full, oa, 16);
    float vb = hi ? s3 : s2;
    float ob = hi ? s2 : s3;
    vb += __shfl_xor_sync(full, ob, 16);
#pragma unroll
    for (int off = 8; off > 0; off >>= 1) {
        va += __shfl_xor_sync(full, va, off);
        vb += __shfl_xor_sync(full, vb, off);
    }
    if (lane == 0) {
        out[e0] = va + bias;
        if (e0 + 2 < E) out[e0 + 2] = vb + bias;
    } else if (lane == 16) {
        if (e0 + 1 < E) out[e0 + 1] = va + bias;
        if (e0 + 3 < E) out[e0 + 3] = vb + bias;
    }
}

extern "C" void kernel_launch(void* const* d_in, const int* in_sizes, int n_in,
                              void* d_out, int out_size)
{
    const float* z_drug = (const float*)d_in[0];
    const float* z_dis  = (const float*)d_in[1];
    const int*   row    = (const int*)  d_in[2];
    const int*   col    = (const int*)  d_in[3];
    const float* W1     = (const float*)d_in[4];
    const float* b1     = (const float*)d_in[5];
    const float* W2     = (const float*)d_in[6];
    const float* b2     = (const float*)d_in[7];
    float* out = (float*)d_out;

    const int n_drug = in_sizes[0] / D;
    const int n_dis  = in_sizes[1] / D;
    const int E      = in_sizes[2];

    __half *dA = nullptr, *dB = nullptr;
    cudaGetSymbolAddress((void**)&dA, g_Ah);
    cudaGetSymbolAddress((void**)&dB, g_Bh);

    const int tiles = (n_drug + 127) / 128 + (n_dis + 127) / 128;
    const bool bucketed = (E <= MAX_E) && (n_drug <= NB * 16);

    if (bucketed) {
        proj_hist_kernel<<<tiles + HB, 256>>>(
            z_drug, z_dis, n_drug, n_dis, W1, b1, dA, dB, row, E, tiles, 1);
        scanbase_kernel<<<NB, 256>>>();
        scatter_kernel<<<HB, 256>>>(row, col, E);
        edge_sorted_kernel<<<NB * SPLIT, 256>>>(W2, b2, out, n_drug);
    } else {
        proj_hist_kernel<<<tiles, 256>>>(
            z_drug, z_dis, n_drug, n_dis, W1, b1, dA, dB, row, E, tiles, 0);
        const int warps  = (E + 3) / 4;
        const int blocks = (warps + 7) / 8;
        edge_kernel_flat<<<blocks, 256>>>(row, col, W2, b2, out, E);
    }
}

// round 8
// speedup vs baseline: 1.0504x; 1.0504x over previous
#include <cuda_runtime.h>
#include <cuda_fp16.h>

#define D 128
#define MAX_DRUG 10000
#define MAX_DIS  15000
#define MAX_E    1048576
#define KC 16            // k-chunk per smem stage (proj)
#define NB 640           // row buckets, 16 rows each (covers 10240 rows)
#define HB 512           // edge chunks (hist/scatter blocks)
#define SPLIT 8          // blocks per bucket in the edge kernel
#define EW 4             // warps per edge block
#define EPB (EW * 16)    // edges per edge-block iteration

// Projected embeddings in fp16 (fp32 math, rounded once).
__device__ __half g_Ah[MAX_DRUG * D];   // z_drug    @ W1[0:128]  + b1
__device__ __half g_Bh[MAX_DIS  * D];   // z_disease @ W1[128:256]
// Counting-sort scratch. g_cnt zero at load; re-zeroed by scatter each launch.
__device__ int  g_cnt[NB];
__device__ int  g_ptr[NB + 1];
__device__ int  g_blkhist[HB * NB];   // [chunk][bucket]
__device__ int  g_base[HB * NB];      // [chunk][bucket] scatter bases
__device__ int2 g_rec[MAX_E];         // (col | r_local<<28, eid)

// ---------------------------------------------------------------------------
// K1: fused projection GEMMs + per-chunk edge-row histograms.
// ---------------------------------------------------------------------------
__global__ __launch_bounds__(256) void proj_hist_kernel(
    const float* __restrict__ Zd, const float* __restrict__ Zs_,
    int n_drug, int n_dis,
    const float* __restrict__ W1, const float* __restrict__ b1,
    __half* __restrict__ A, __half* __restrict__ B,
    const int* __restrict__ row, int E, int tiles, int do_hist)
{
    const int t = threadIdx.x;

    if ((int)blockIdx.x >= tiles) {                 // ---- histogram blocks
        if (!do_hist) return;
        __shared__ int hc[NB];
        const int hb = blockIdx.x - tiles;
        const int cs = (E + HB - 1) / HB;
        const int e0 = hb * cs;
        const int e1 = min(e0 + cs, E);
        for (int i = t; i < NB; i += 256) hc[i] = 0;
        __syncthreads();
        for (int e = e0 + t; e < e1; e += 256)
            atomicAdd(&hc[row[e] >> 4], 1);
        __syncthreads();
        for (int i = t; i < NB; i += 256) {
            const int v = hc[i];
            g_blkhist[hb * NB + i] = v;
            if (v) atomicAdd(&g_cnt[i], v);
        }
        return;
    }

    // ---- projection blocks
    const int tiles_drug = (n_drug + 127) / 128;
    const float* Z;
    __half* out;
    int N, koff, addb;
    int tile = blockIdx.x;
    if (tile < tiles_drug) { Z = Zd;  out = A; N = n_drug; koff = 0;   addb = 1; }
    else { tile -= tiles_drug; Z = Zs_; out = B; N = n_dis; koff = 128; addb = 0; }
    const int r0 = tile * 128;

    __shared__ float Zt[KC][128];
    __shared__ float Wt[KC][128];

    const int tx = t & 15;
    const int ty = t >> 4;

    float acc[8][8];
#pragma unroll
    for (int i = 0; i < 8; i++)
#pragma unroll
        for (int j = 0; j < 8; j++) acc[i][j] = 0.f;

    for (int kc = 0; kc < D; kc += KC) {
        __syncthreads();
#pragma unroll
        for (int i = t; i < 512; i += 256) {
            int rr = i & 127;
            int k4 = i >> 7;
            float4 v = make_float4(0.f, 0.f, 0.f, 0.f);
            if (r0 + rr < N)
                v = *reinterpret_cast<const float4*>(
                        Z + (size_t)(r0 + rr) * D + kc + k4 * 4);
            Zt[k4 * 4 + 0][rr] = v.x;
            Zt[k4 * 4 + 1][rr] = v.y;
            Zt[k4 * 4 + 2][rr] = v.z;
            Zt[k4 * 4 + 3][rr] = v.w;
        }
#pragma unroll
        for (int i = t; i < 512; i += 256) {
            int kk = i >> 5;
            int c4 = i & 31;
            *reinterpret_cast<float4*>(&Wt[kk][c4 * 4]) =
                *reinterpret_cast<const float4*>(
                    W1 + (size_t)(koff + kc + kk) * D + c4 * 4);
        }
        __syncthreads();

#pragma unroll
        for (int kk = 0; kk < KC; kk++) {
            float af[8], bf[8];
            *reinterpret_cast<float4*>(af)     = *reinterpret_cast<float4*>(&Zt[kk][ty * 8]);
            *reinterpret_cast<float4*>(af + 4) = *reinterpret_cast<float4*>(&Zt[kk][ty * 8 + 4]);
            *reinterpret_cast<float4*>(bf)     = *reinterpret_cast<float4*>(&Wt[kk][tx * 8]);
            *reinterpret_cast<float4*>(bf + 4) = *reinterpret_cast<float4*>(&Wt[kk][tx * 8 + 4]);
#pragma unroll
            for (int i = 0; i < 8; i++)
#pragma unroll
                for (int j = 0; j < 8; j++)
                    acc[i][j] = fmaf(af[i], bf[j], acc[i][j]);
        }
    }

    float bias[8];
#pragma unroll
    for (int j = 0; j < 8; j++) bias[j] = addb ? b1[tx * 8 + j] : 0.f;

#pragma unroll
    for (int i = 0; i < 8; i++) {
        int r = r0 + ty * 8 + i;
        if (r < N) {
            __half2 h[4];
#pragma unroll
            for (int j = 0; j < 4; j++)
                h[j] = __floats2half2_rn(acc[i][2 * j]     + bias[2 * j],
                                         acc[i][2 * j + 1] + bias[2 * j + 1]);
            *reinterpret_cast<uint4*>(out + (size_t)r * D + tx * 8) =
                *reinterpret_cast<uint4*>(h);
        }
    }
}

// ---------------------------------------------------------------------------
// K2: merged bucket-prefix + chunk-base kernel. One block per bucket b.
// ---------------------------------------------------------------------------
__global__ __launch_bounds__(256) void scanbase_kernel()
{
    const int b = blockIdx.x;
    const int t = threadIdx.x;

    __shared__ int sP[256], sT[256];
    int p = 0, tot = 0;
    for (int i = t; i < NB; i += 256) {
        const int v = g_cnt[i];
        tot += v;
        if (i < b) p += v;
    }
    sP[t] = p;
    sT[t] = tot;
    __syncthreads();
    for (int off = 128; off > 0; off >>= 1) {
        if (t < off) { sP[t] += sP[t + off]; sT[t] += sT[t + off]; }
        __syncthreads();
    }
    const int ptr_b = sP[0];
    if (t == 0) {
        g_ptr[b] = ptr_b;
        if (b == 0) g_ptr[NB] = sT[0];
    }

    __shared__ int sA[HB], sB[HB];
    const int v0 = g_blkhist[t * NB + b];
    const int v1 = g_blkhist[(t + 256) * NB + b];
    sA[t] = v0;
    sA[t + 256] = v1;
    __syncthreads();

    int* src = sA;
    int* dst = sB;
#pragma unroll
    for (int off = 1; off < HB; off <<= 1) {
        int x0 = src[t];
        if (t >= off) x0 += src[t - off];
        int x1 = src[t + 256];
        if (t + 256 >= off) x1 += src[t + 256 - off];
        dst[t] = x0;
        dst[t + 256] = x1;
        __syncthreads();
        int* tmp = src; src = dst; dst = tmp;
    }
    g_base[t * NB + b]         = ptr_b + src[t] - v0;
    g_base[(t + 256) * NB + b] = ptr_b + src[t + 256] - v1;
}

// ---------------------------------------------------------------------------
// K3: scatter — smem atomics against precomputed bases; re-arms g_cnt.
// ---------------------------------------------------------------------------
__global__ __launch_bounds__(256) void scatter_kernel(
    const int* __restrict__ row, const int* __restrict__ col, int E)
{
    __shared__ int soff[NB];
    const int hb = blockIdx.x;
    const int t  = threadIdx.x;
    const int cs = (E + HB - 1) / HB;
    const int e0 = hb * cs;
    const int e1 = min(e0 + cs, E);

    if (t == 0)
        for (int i = hb; i < NB; i += HB) g_cnt[i] = 0;

    for (int i = t; i < NB; i += 256) soff[i] = g_base[hb * NB + i];
    __syncthreads();

    for (int e = e0 + t; e < e1; e += 256) {
        const int r = row[e];
        const int c = col[e];
        const int p = atomicAdd(&soff[r >> 4], 1);
        g_rec[p] = make_int2(c | ((r & 15) << 28), e);
    }
}

// ---------------------------------------------------------------------------
// K4: bucketed edge compute. 128-thread blocks, SPLIT per bucket.
// 16 edges per warp-iteration (8 pairs -> 8 B-LDG.128 in flight) with
// software-pipelined record loads (next iter's records issued before
// current iter's compute).
// ---------------------------------------------------------------------------
__global__ __launch_bounds__(128) void edge_sorted_kernel(
    const float* __restrict__ W2, const float* __restrict__ b2,
    float* __restrict__ out, int n_drug)
{
    __shared__ uint4 As4[16 * 16];

    const int t    = threadIdx.x;
    const int b    = blockIdx.x / SPLIT;
    const int part = blockIdx.x % SPLIT;

    {   // stage this bucket's 16 A rows (4KB), 2 chunks per thread
        const uint4* A16 = reinterpret_cast<const uint4*>(g_Ah);
#pragma unroll
        for (int i = 0; i < 2; i++) {
            const int idx = t + i * 128;
            const int r = b * 16 + (idx >> 4);
            As4[idx] = (r < n_drug) ? A16[r * 16 + (idx & 15)]
                                    : make_uint4(0u, 0u, 0u, 0u);
        }
    }
    __syncthreads();

    const int s0  = g_ptr[b];
    const int len = g_ptr[b + 1] - s0;
    const int q0  = s0 + (int)(((long long)len * part) / SPLIT);
    const int q1  = s0 + (int)(((long long)len * (part + 1)) / SPLIT);
    if (q0 >= q1) return;

    const int lane = t & 31;
    const int wid  = t >> 5;         // 0..EW-1
    const int j    = lane & 15;      // 16B chunk within a 256B row
    const int hi   = lane >> 4;      // 0 = even edge of pair, 1 = odd

    const float4 wa = reinterpret_cast<const float4*>(W2)[j * 2];
    const float4 wb = reinterpret_cast<const float4*>(W2)[j * 2 + 1];
    const __half2 w0  = __floats2half2_rn(wa.x, wa.y);
    const __half2 w1  = __floats2half2_rn(wa.z, wa.w);
    const __half2 w2h = __floats2half2_rn(wb.x, wb.y);
    const __half2 w3  = __floats2half2_rn(wb.z, wb.w);
    const float bias = b2[0];
    const __half2 zero = __float2half2_rn(0.f);
    const uint4* __restrict__ B16 = reinterpret_cast<const uint4*>(g_Bh);
    const unsigned full = 0xffffffffu;

    auto pair_dot = [&](const uint4& a, const uint4& bv) -> float {
        __half2 h0 = __hmax2(__hadd2(*reinterpret_cast<const __half2*>(&a.x),
                                     *reinterpret_cast<const __half2*>(&bv.x)), zero);
        __half2 h1 = __hmax2(__hadd2(*reinterpret_cast<const __half2*>(&a.y),
                                     *reinterpret_cast<const __half2*>(&bv.y)), zero);
        __half2 h2 = __hmax2(__hadd2(*reinterpret_cast<const __half2*>(&a.z),
                                     *reinterpret_cast<const __half2*>(&bv.z)), zero);
        __half2 h3 = __hmax2(__hadd2(*reinterpret_cast<const __half2*>(&a.w),
                                     *reinterpret_cast<const __half2*>(&bv.w)), zero);
        __half2 acc0 = __hfma2(h1, w1, __hmul2(h0, w0));
        __half2 acc1 = __hfma2(h3, w3, __hmul2(h2, w2h));
        float2 f0 = __half22float2(acc0);
        float2 f1 = __half22float2(acc1);
        return (f0.x + f0.y) + (f1.x + f1.y);
    };

    // 16 edges per warp-iteration, records software-pipelined.
    int base = q0 + wid * 16;
    int2 rec = make_int2(0, 0);
    if (base < q1 && lane < 16)
        rec = g_rec[min(base + lane, q1 - 1)];

    for (; base < q1; base += EPB) {
        // Prefetch next iteration's records before any compute.
        const int nbase = base + EPB;
        int2 recn = make_int2(0, 0);
        if (nbase < q1 && lane < 16)
            recn = g_rec[min(nbase + lane, q1 - 1)];

        const int n = min(16, q1 - base);

        // Broadcast pair records: pair p -> record 2p+hi.
        int rx[8], re[8];
#pragma unroll
        for (int p = 0; p < 8; p++) {
            rx[p] = __shfl_sync(full, rec.x, 2 * p + hi);
            re[p] = __shfl_sync(full, rec.y, 2 * p + hi);
        }

        // Front-batched B gathers: 8 independent LDG.128 in flight.
        uint4 bv[8];
#pragma unroll
        for (int p = 0; p < 8; p++) {
            const int c = rx[p] & 0x0FFFFFFF;
            bv[p] = B16[(size_t)c * 16 + j];
        }

        // A from smem, lazily, + dot.
        float s[8];
#pragma unroll
        for (int p = 0; p < 8; p++) {
            const int rl = ((unsigned)rx[p]) >> 28;
            s[p] = pair_dot(As4[rl * 16 + j], bv[p]);
        }

        // Butterfly within 16-lane halves.
#pragma unroll
        for (int off = 8; off > 0; off >>= 1) {
#pragma unroll
            for (int p = 0; p < 8; p++)
                s[p] += __shfl_xor_sync(full, s[p], off);
        }

        if (j == 0) {   // lanes 0 (even edges) and 16 (odd edges)
#pragma unroll
            for (int p = 0; p < 8; p++)
                if (2 * p + hi < n) out[re[p]] = s[p] + bias;
        }

        rec = recn;
    }
}

// ---------------------------------------------------------------------------
// Fallback flat edge kernel (round-4, known-good) for odd shapes.
// ---------------------------------------------------------------------------
__global__ __launch_bounds__(256) void edge_kernel_flat(
    const int* __restrict__ row, const int* __restrict__ col,
    const float* __restrict__ W2, const float* __restrict__ b2,
    float* __restrict__ out, int E)
{
    const int lane = threadIdx.x & 31;
    const int warp = blockIdx.x * 8 + (threadIdx.x >> 5);
    const int e0 = warp * 4;
    if (e0 >= E) return;

    const float4 w2 = reinterpret_cast<const float4*>(W2)[lane];
    const float bias = b2[0];
    const int last = E - 1;

    const int r0i = row[e0];
    const int c0i = col[e0];
    const int r1i = row[min(e0 + 1, last)];
    const int c1i = col[min(e0 + 1, last)];
    const int r2i = row[min(e0 + 2, last)];
    const int c2i = col[min(e0 + 2, last)];
    const int r3i = row[min(e0 + 3, last)];
    const int c3i = col[min(e0 + 3, last)];

    const uint2* __restrict__ Ah = reinterpret_cast<const uint2*>(g_Ah);
    const uint2* __restrict__ Bh = reinterpret_cast<const uint2*>(g_Bh);
    const uint2 a0 = Ah[(size_t)r0i * 32 + lane];
    const uint2 b0 = Bh[(size_t)c0i * 32 + lane];
    const uint2 a1 = Ah[(size_t)r1i * 32 + lane];
    const uint2 b1v = Bh[(size_t)c1i * 32 + lane];
    const uint2 a2 = Ah[(size_t)r2i * 32 + lane];
    const uint2 b2v = Bh[(size_t)c2i * 32 + lane];
    const uint2 a3 = Ah[(size_t)r3i * 32 + lane];
    const uint2 b3v = Bh[(size_t)c3i * 32 + lane];

    const __half2 zero = __float2half2_rn(0.f);
    auto edge_dot = [&](uint2 a, uint2 b) -> float {
        __half2 al = *reinterpret_cast<__half2*>(&a.x);
        __half2 ah = *reinterpret_cast<__half2*>(&a.y);
        __half2 bl = *reinterpret_cast<__half2*>(&b.x);
        __half2 bh = *reinterpret_cast<__half2*>(&b.y);
        __half2 h0 = __hmax2(__hadd2(al, bl), zero);
        __half2 h1 = __hmax2(__hadd2(ah, bh), zero);
        float2 f0 = __half22float2(h0);
        float2 f1 = __half22float2(h1);
        return f0.x * w2.x + f0.y * w2.y + f1.x * w2.z + f1.y * w2.w;
    };

    float s0 = edge_dot(a0, b0);
    float s1 = edge_dot(a1, b1v);
    float s2 = edge_dot(a2, b2v);
    float s3 = edge_dot(a3, b3v);

    const unsigned full = 0xffffffffu;
    const bool hi = (lane & 16) != 0;
    float va = hi ? s1 : s0;
    float oa = hi ? s0 : s1;
    va += __shfl_xor_sync(full, oa, 16);
    float vb = hi ? s3 : s2;
    float ob = hi ? s2 : s3;
    vb += __shfl_xor_sync(full, ob, 16);
#pragma unroll
    for (int off = 8; off > 0; off >>= 1) {
        va += __shfl_xor_sync(full, va, off);
        vb += __shfl_xor_sync(full, vb, off);
    }
    if (lane == 0) {
        out[e0] = va + bias;
        if (e0 + 2 < E) out[e0 + 2] = vb + bias;
    } else if (lane == 16) {
        if (e0 + 1 < E) out[e0 + 1] = va + bias;
        if (e0 + 3 < E) out[e0 + 3] = vb + bias;
    }
}

extern "C" void kernel_launch(void* const* d_in, const int* in_sizes, int n_in,
                              void* d_out, int out_size)
{
    const float* z_drug = (const float*)d_in[0];
    const float* z_dis  = (const float*)d_in[1];
    const int*   row    = (const int*)  d_in[2];
    const int*   col    = (const int*)  d_in[3];
    const float* W1     = (const float*)d_in[4];
    const float* b1     = (const float*)d_in[5];
    const float* W2     = (const float*)d_in[6];
    const float* b2     = (const float*)d_in[7];
    float* out = (float*)d_out;

    const int n_drug = in_sizes[0] / D;
    const int n_dis  = in_sizes[1] / D;
    const int E      = in_sizes[2];

    __half *dA = nullptr, *dB = nullptr;
    cudaGetSymbolAddress((void**)&dA, g_Ah);
    cudaGetSymbolAddress((void**)&dB, g_Bh);

    const int tiles = (n_drug + 127) / 128 + (n_dis + 127) / 128;
    const bool bucketed = (E <= MAX_E) && (n_drug <= NB * 16);

    if (bucketed) {
        proj_hist_kernel<<<tiles + HB, 256>>>(
            z_drug, z_dis, n_drug, n_dis, W1, b1, dA, dB, row, E, tiles, 1);
        scanbase_kernel<<<NB, 256>>>();
        scatter_kernel<<<HB, 256>>>(row, col, E);
        edge_sorted_kernel<<<NB * SPLIT, 128>>>(W2, b2, out, n_drug);
    } else {
        proj_hist_kernel<<<tiles, 256>>>(
            z_drug, z_dis, n_drug, n_dis, W1, b1, dA, dB, row, E, tiles, 0);
        const int warps  = (E + 3) / 4;
        const int blocks = (warps + 7) / 8;
        edge_kernel_flat<<<blocks, 256>>>(row, col, W2, b2, out, E);
    }
}

// round 10
// speedup vs baseline: 1.1083x; 1.0552x over previous
#include <cuda_runtime.h>
#include <cuda_fp16.h>

#define D 128
#define MAX_DRUG 10000
#define MAX_DIS  15000
#define MAX_E    1048576
#define KC 16            // k-chunk per smem stage (proj)
#define NB 640           // row buckets, 16 rows each (covers 10240 rows)
#define HB 512           // edge chunks (hist/scatter blocks)
#define SPLIT 8          // blocks per bucket in the edge kernel
#define EW 4             // warps per edge block
#define EPB (EW * 16)    // edges per edge-block iteration

// Projected embeddings in fp16 (fp32 math, rounded once).
__device__ __half g_Ah[MAX_DRUG * D];   // z_drug    @ W1[0:128]  + b1
__device__ __half g_Bh[MAX_DIS  * D];   // z_disease @ W1[128:256]
// Counting-sort scratch. g_cnt zero at load; re-zeroed by scatter each launch.
__device__ int  g_cnt[NB];
__device__ int  g_ptr[NB + 1];
__device__ int  g_blkhist[NB * HB];   // [bucket][chunk]  (scanbase-coalesced)
__device__ int  g_base[HB * NB];      // [chunk][bucket]  (scatter-coalesced)
__device__ int2 g_rec[MAX_E];         // (col | r_local<<28, eid)

// ---------------------------------------------------------------------------
// K1: fused projection GEMMs + per-chunk edge-row histograms.
// ---------------------------------------------------------------------------
__global__ __launch_bounds__(256) void proj_hist_kernel(
    const float* __restrict__ Zd, const float* __restrict__ Zs_,
    int n_drug, int n_dis,
    const float* __restrict__ W1, const float* __restrict__ b1,
    __half* __restrict__ A, __half* __restrict__ B,
    const int* __restrict__ row, int E, int tiles, int do_hist)
{
    const int t = threadIdx.x;

    if ((int)blockIdx.x >= tiles) {                 // ---- histogram blocks
        if (!do_hist) return;
        __shared__ int hc[NB];
        const int hb = blockIdx.x - tiles;
        const int cs = (E + HB - 1) / HB;
        const int e0 = hb * cs;
        const int e1 = min(e0 + cs, E);
        for (int i = t; i < NB; i += 256) hc[i] = 0;
        __syncthreads();
        for (int e = e0 + t; e < e1; e += 256)
            atomicAdd(&hc[row[e] >> 4], 1);
        __syncthreads();
        for (int i = t; i < NB; i += 256) {
            const int v = hc[i];
            g_blkhist[i * HB + hb] = v;            // transposed layout
            if (v) atomicAdd(&g_cnt[i], v);        // fire-and-forget RED
        }
        return;
    }

    // ---- projection blocks
    const int tiles_drug = (n_drug + 127) / 128;
    const float* Z;
    __half* out;
    int N, koff, addb;
    int tile = blockIdx.x;
    if (tile < tiles_drug) { Z = Zd;  out = A; N = n_drug; koff = 0;   addb = 1; }
    else { tile -= tiles_drug; Z = Zs_; out = B; N = n_dis; koff = 128; addb = 0; }
    const int r0 = tile * 128;

    __shared__ float Zt[KC][128];
    __shared__ float Wt[KC][128];

    const int tx = t & 15;
    const int ty = t >> 4;

    float acc[8][8];
#pragma unroll
    for (int i = 0; i < 8; i++)
#pragma unroll
        for (int j = 0; j < 8; j++) acc[i][j] = 0.f;

    for (int kc = 0; kc < D; kc += KC) {
        __syncthreads();
#pragma unroll
        for (int i = t; i < 512; i += 256) {
            int rr = i & 127;
            int k4 = i >> 7;
            float4 v = make_float4(0.f, 0.f, 0.f, 0.f);
            if (r0 + rr < N)
                v = *reinterpret_cast<const float4*>(
                        Z + (size_t)(r0 + rr) * D + kc + k4 * 4);
            Zt[k4 * 4 + 0][rr] = v.x;
            Zt[k4 * 4 + 1][rr] = v.y;
            Zt[k4 * 4 + 2][rr] = v.z;
            Zt[k4 * 4 + 3][rr] = v.w;
        }
#pragma unroll
        for (int i = t; i < 512; i += 256) {
            int kk = i >> 5;
            int c4 = i & 31;
            *reinterpret_cast<float4*>(&Wt[kk][c4 * 4]) =
                *reinterpret_cast<const float4*>(
                    W1 + (size_t)(koff + kc + kk) * D + c4 * 4);
        }
        __syncthreads();

#pragma unroll
        for (int kk = 0; kk < KC; kk++) {
            float af[8], bf[8];
            *reinterpret_cast<float4*>(af)     = *reinterpret_cast<float4*>(&Zt[kk][ty * 8]);
            *reinterpret_cast<float4*>(af + 4) = *reinterpret_cast<float4*>(&Zt[kk][ty * 8 + 4]);
            *reinterpret_cast<float4*>(bf)     = *reinterpret_cast<float4*>(&Wt[kk][tx * 8]);
            *reinterpret_cast<float4*>(bf + 4) = *reinterpret_cast<float4*>(&Wt[kk][tx * 8 + 4]);
#pragma unroll
            for (int i = 0; i < 8; i++)
#pragma unroll
                for (int j = 0; j < 8; j++)
                    acc[i][j] = fmaf(af[i], bf[j], acc[i][j]);
        }
    }

    float bias[8];
#pragma unroll
    for (int j = 0; j < 8; j++) bias[j] = addb ? b1[tx * 8 + j] : 0.f;

#pragma unroll
    for (int i = 0; i < 8; i++) {
        int r = r0 + ty * 8 + i;
        if (r < N) {
            __half2 h[4];
#pragma unroll
            for (int j = 0; j < 4; j++)
                h[j] = __floats2half2_rn(acc[i][2 * j]     + bias[2 * j],
                                         acc[i][2 * j + 1] + bias[2 * j + 1]);
            *reinterpret_cast<uint4*>(out + (size_t)r * D + tx * 8) =
                *reinterpret_cast<uint4*>(h);
        }
    }
}

// ---------------------------------------------------------------------------
// K2: merged bucket-prefix + chunk-base. One block per bucket b; chunk
// counts read contiguously. Originals snapshotted to registers BEFORE the
// ping-pong scan mutates sA (the round-9 bug).
// ---------------------------------------------------------------------------
__global__ __launch_bounds__(256) void scanbase_kernel()
{
    const int b = blockIdx.x;
    const int t = threadIdx.x;

    __shared__ int sP[256], sT[256];
    int p = 0, tot = 0;
    for (int i = t; i < NB; i += 256) {
        const int v = g_cnt[i];
        tot += v;
        if (i < b) p += v;
    }
    sP[t] = p;
    sT[t] = tot;
    __syncthreads();
    for (int off = 128; off > 0; off >>= 1) {
        if (t < off) { sP[t] += sP[t + off]; sT[t] += sT[t + off]; }
        __syncthreads();
    }
    const int ptr_b = sP[0];
    if (t == 0) {
        g_ptr[b] = ptr_b;
        if (b == 0) g_ptr[NB] = sT[0];
    }

    __shared__ int sA[HB], sB[HB];
    const int2 v2 = *reinterpret_cast<const int2*>(&g_blkhist[b * HB + t * 2]);
    sA[t * 2]     = v2.x;
    sA[t * 2 + 1] = v2.y;
    __syncthreads();
    // Snapshot originals in scan index space BEFORE sA is mutated.
    const int v0 = sA[t];
    const int v1 = sA[t + 256];
    __syncthreads();

    int* src = sA;
    int* dst = sB;
#pragma unroll
    for (int off = 1; off < HB; off <<= 1) {
        int x0 = src[t];
        if (t >= off) x0 += src[t - off];
        int x1 = src[t + 256];
        if (t + 256 >= off) x1 += src[t + 256 - off];
        dst[t] = x0;
        dst[t + 256] = x1;
        __syncthreads();
        int* tmp = src; src = dst; dst = tmp;
    }
    g_base[t * NB + b]         = ptr_b + src[t] - v0;         // exclusive
    g_base[(t + 256) * NB + b] = ptr_b + src[t + 256] - v1;
}

// ---------------------------------------------------------------------------
// K3: scatter — 4-edge ILP, smem atomics against precomputed bases;
// re-arms g_cnt.
// ---------------------------------------------------------------------------
__global__ __launch_bounds__(256) void scatter_kernel(
    const int* __restrict__ row, const int* __restrict__ col, int E)
{
    __shared__ int soff[NB];
    const int hb = blockIdx.x;
    const int t  = threadIdx.x;
    const int cs = (E + HB - 1) / HB;
    const int e0 = hb * cs;
    const int e1 = min(e0 + cs, E);

    if (t < (NB + HB - 1) / HB) {
        const int i = hb + t * HB;
        if (i < NB) g_cnt[i] = 0;
    }

    for (int i = t; i < NB; i += 256) soff[i] = g_base[hb * NB + i];
    __syncthreads();

    int e = e0 + t;
    for (; e + 768 < e1; e += 1024) {
        const int r0v = row[e];
        const int r1v = row[e + 256];
        const int r2v = row[e + 512];
        const int r3v = row[e + 768];
        const int c0v = col[e];
        const int c1v = col[e + 256];
        const int c2v = col[e + 512];
        const int c3v = col[e + 768];
        const int p0 = atomicAdd(&soff[r0v >> 4], 1);
        const int p1 = atomicAdd(&soff[r1v >> 4], 1);
        const int p2 = atomicAdd(&soff[r2v >> 4], 1);
        const int p3 = atomicAdd(&soff[r3v >> 4], 1);
        g_rec[p0] = make_int2(c0v | ((r0v & 15) << 28), e);
        g_rec[p1] = make_int2(c1v | ((r1v & 15) << 28), e + 256);
        g_rec[p2] = make_int2(c2v | ((r2v & 15) << 28), e + 512);
        g_rec[p3] = make_int2(c3v | ((r3v & 15) << 28), e + 768);
    }
    for (; e < e1; e += 256) {
        const int r = row[e];
        const int c = col[e];
        const int p = atomicAdd(&soff[r >> 4], 1);
        g_rec[p] = make_int2(c | ((r & 15) << 28), e);
    }
}

// ---------------------------------------------------------------------------
// K4: bucketed edge compute. 128-thread blocks, SPLIT per bucket,
// 16 edges per warp-iteration. Record ownership: lane p (p<8) owns edge
// base+p, lane 16+p owns edge base+8+p — after the in-half butterfly the
// owning lane holds its own result, so writes need no eid broadcasts.
// ---------------------------------------------------------------------------
__global__ __launch_bounds__(128) void edge_sorted_kernel(
    const float* __restrict__ W2, const float* __restrict__ b2,
    float* __restrict__ out, int n_drug)
{
    __shared__ uint4 As4[16 * 16];

    const int t    = threadIdx.x;
    const int b    = blockIdx.x / SPLIT;
    const int part = blockIdx.x % SPLIT;

    {   // stage this bucket's 16 A rows (4KB)
        const uint4* A16 = reinterpret_cast<const uint4*>(g_Ah);
#pragma unroll
        for (int i = 0; i < 2; i++) {
            const int idx = t + i * 128;
            const int r = b * 16 + (idx >> 4);
            As4[idx] = (r < n_drug) ? A16[r * 16 + (idx & 15)]
                                    : make_uint4(0u, 0u, 0u, 0u);
        }
    }
    __syncthreads();

    const int s0  = g_ptr[b];
    const int len = g_ptr[b + 1] - s0;
    const int q0  = s0 + (int)(((long long)len * part) / SPLIT);
    const int q1  = s0 + (int)(((long long)len * (part + 1)) / SPLIT);
    if (q0 >= q1) return;

    const int lane = t & 31;
    const int wid  = t >> 5;
    const int j    = lane & 15;      // 16B chunk within a 256B row
    const int hi   = lane >> 4;      // half-warp id

    // Record loaders: lanes 0-7 -> edges base+0..7; lanes 16-23 -> base+8..15
    const bool loader  = (lane & 8) == 0;
    const int  loadoff = (lane & 7) + hi * 8;

    const float4 wa = reinterpret_cast<const float4*>(W2)[j * 2];
    const float4 wb = reinterpret_cast<const float4*>(W2)[j * 2 + 1];
    const __half2 w0  = __floats2half2_rn(wa.x, wa.y);
    const __half2 w1  = __floats2half2_rn(wa.z, wa.w);
    const __half2 w2h = __floats2half2_rn(wb.x, wb.y);
    const __half2 w3  = __floats2half2_rn(wb.z, wb.w);
    const float bias = b2[0];
    const __half2 zero = __float2half2_rn(0.f);
    const uint4* __restrict__ B16 = reinterpret_cast<const uint4*>(g_Bh);
    const unsigned full = 0xffffffffu;

    auto pair_dot = [&](const uint4& a, const uint4& bv) -> float {
        __half2 h0 = __hmax2(__hadd2(*reinterpret_cast<const __half2*>(&a.x),
                                     *reinterpret_cast<const __half2*>(&bv.x)), zero);
        __half2 h1 = __hmax2(__hadd2(*reinterpret_cast<const __half2*>(&a.y),
                                     *reinterpret_cast<const __half2*>(&bv.y)), zero);
        __half2 h2 = __hmax2(__hadd2(*reinterpret_cast<const __half2*>(&a.z),
                                     *reinterpret_cast<const __half2*>(&bv.z)), zero);
        __half2 h3 = __hmax2(__hadd2(*reinterpret_cast<const __half2*>(&a.w),
                                     *reinterpret_cast<const __half2*>(&bv.w)), zero);
        __half2 acc0 = __hfma2(h1, w1, __hmul2(h0, w0));
        __half2 acc1 = __hfma2(h3, w3, __hmul2(h2, w2h));
        float2 f0 = __half22float2(acc0);
        float2 f1 = __half22float2(acc1);
        return (f0.x + f0.y) + (f1.x + f1.y);
    };

    int base = q0 + wid * 16;
    int2 rec = make_int2(0, 0);
    if (base < q1 && loader)
        rec = g_rec[min(base + loadoff, q1 - 1)];

    for (; base < q1; base += EPB) {
        const int nbase = base + EPB;
        int2 recn = make_int2(0, 0);
        if (nbase < q1 && loader)
            recn = g_rec[min(nbase + loadoff, q1 - 1)];

        const int n = min(16, q1 - base);

        // Pair p: low half uses record in lane p (edge p), high half uses
        // lane 16+p (edge 8+p).
        int rx[8];
#pragma unroll
        for (int p = 0; p < 8; p++)
            rx[p] = __shfl_sync(full, rec.x, p + hi * 16);

        // Front-batched B gathers: 8 independent LDG.128 in flight.
        uint4 bv[8];
#pragma unroll
        for (int p = 0; p < 8; p++) {
            const int c = rx[p] & 0x0FFFFFFF;
            bv[p] = B16[(size_t)c * 16 + j];
        }

        float s[8];
#pragma unroll
        for (int p = 0; p < 8; p++) {
            const int rl = ((unsigned)rx[p]) >> 28;
            s[p] = pair_dot(As4[rl * 16 + j], bv[p]);
        }

        // Butterfly within 16-lane halves.
#pragma unroll
        for (int off = 8; off > 0; off >>= 1) {
#pragma unroll
            for (int p = 0; p < 8; p++)
                s[p] += __shfl_xor_sync(full, s[p], off);
        }

        // Owning-lane writes: lane p -> edge base+p, lane 16+p -> base+8+p.
#pragma unroll
        for (int p = 0; p < 8; p++) {
            if ((lane & 15) == p) {
                const int eidx = p + hi * 8;
                if (eidx < n) out[rec.y] = s[p] + bias;
            }
        }

        rec = recn;
    }
}

// ---------------------------------------------------------------------------
// Fallback flat edge kernel (round-4, known-good) for odd shapes.
// ---------------------------------------------------------------------------
__global__ __launch_bounds__(256) void edge_kernel_flat(
    const int* __restrict__ row, const int* __restrict__ col,
    const float* __restrict__ W2, const float* __restrict__ b2,
    float* __restrict__ out, int E)
{
    const int lane = threadIdx.x & 31;
    const int warp = blockIdx.x * 8 + (threadIdx.x >> 5);
    const int e0 = warp * 4;
    if (e0 >= E) return;

    const float4 w2 = reinterpret_cast<const float4*>(W2)[lane];
    const float bias = b2[0];
    const int last = E - 1;

    const int r0i = row[e0];
    const int c0i = col[e0];
    const int r1i = row[min(e0 + 1, last)];
    const int c1i = col[min(e0 + 1, last)];
    const int r2i = row[min(e0 + 2, last)];
    const int c2i = col[min(e0 + 2, last)];
    const int r3i = row[min(e0 + 3, last)];
    const int c3i = col[min(e0 + 3, last)];

    const uint2* __restrict__ Ah = reinterpret_cast<const uint2*>(g_Ah);
    const uint2* __restrict__ Bh = reinterpret_cast<const uint2*>(g_Bh);
    const uint2 a0 = Ah[(size_t)r0i * 32 + lane];
    const uint2 b0 = Bh[(size_t)c0i * 32 + lane];
    const uint2 a1 = Ah[(size_t)r1i * 32 + lane];
    const uint2 b1v = Bh[(size_t)c1i * 32 + lane];
    const uint2 a2 = Ah[(size_t)r2i * 32 + lane];
    const uint2 b2v = Bh[(size_t)c2i * 32 + lane];
    const uint2 a3 = Ah[(size_t)r3i * 32 + lane];
    const uint2 b3v = Bh[(size_t)c3i * 32 + lane];

    const __half2 zero = __float2half2_rn(0.f);
    auto edge_dot = [&](uint2 a, uint2 b) -> float {
        __half2 al = *reinterpret_cast<__half2*>(&a.x);
        __half2 ah = *reinterpret_cast<__half2*>(&a.y);
        __half2 bl = *reinterpret_cast<__half2*>(&b.x);
        __half2 bh = *reinterpret_cast<__half2*>(&b.y);
        __half2 h0 = __hmax2(__hadd2(al, bl), zero);
        __half2 h1 = __hmax2(__hadd2(ah, bh), zero);
        float2 f0 = __half22float2(h0);
        float2 f1 = __half22float2(h1);
        return f0.x * w2.x + f0.y * w2.y + f1.x * w2.z + f1.y * w2.w;
    };

    float s0 = edge_dot(a0, b0);
    float s1 = edge_dot(a1, b1v);
    float s2 = edge_dot(a2, b2v);
    float s3 = edge_dot(a3, b3v);

    const unsigned full = 0xffffffffu;
    const bool hi = (lane & 16) != 0;
    float va = hi ? s1 : s0;
    float oa = hi ? s0 : s1;
    va += __shfl_xor_sync(full, oa, 16);
    float vb = hi ? s3 : s2;
    float ob = hi ? s2 : s3;
    vb += __shfl_xor_sync(full, ob, 16);
#pragma unroll
    for (int off = 8; off > 0; off >>= 1) {
        va += __shfl_xor_sync(full, va, off);
        vb += __shfl_xor_sync(full, vb, off);
    }
    if (lane == 0) {
        out[e0] = va + bias;
        if (e0 + 2 < E) out[e0 + 2] = vb + bias;
    } else if (lane == 16) {
        if (e0 + 1 < E) out[e0 + 1] = va + bias;
        if (e0 + 3 < E) out[e0 + 3] = vb + bias;
    }
}

extern "C" void kernel_launch(void* const* d_in, const int* in_sizes, int n_in,
                              void* d_out, int out_size)
{
    const float* z_drug = (const float*)d_in[0];
    const float* z_dis  = (const float*)d_in[1];
    const int*   row    = (const int*)  d_in[2];
    const int*   col    = (const int*)  d_in[3];
    const float* W1     = (const float*)d_in[4];
    const float* b1     = (const float*)d_in[5];
    const float* W2     = (const float*)d_in[6];
    const float* b2     = (const float*)d_in[7];
    float* out = (float*)d_out;

    const int n_drug = in_sizes[0] / D;
    const int n_dis  = in_sizes[1] / D;
    const int E      = in_sizes[2];

    __half *dA = nullptr, *dB = nullptr;
    cudaGetSymbolAddress((void**)&dA, g_Ah);
    cudaGetSymbolAddress((void**)&dB, g_Bh);

    const int tiles = (n_drug + 127) / 128 + (n_dis + 127) / 128;
    const bool bucketed = (E <= MAX_E) && (n_drug <= NB * 16);

    if (bucketed) {
        proj_hist_kernel<<<tiles + HB, 256>>>(
            z_drug, z_dis, n_drug, n_dis, W1, b1, dA, dB, row, E, tiles, 1);
        scanbase_kernel<<<NB, 256>>>();
        scatter_kernel<<<HB, 256>>>(row, col, E);
        edge_sorted_kernel<<<NB * SPLIT, 128>>>(W2, b2, out, n_drug);
    } else {
        proj_hist_kernel<<<tiles, 256>>>(
            z_drug, z_dis, n_drug, n_dis, W1, b1, dA, dB, row, E, tiles, 0);
        const int warps  = (E + 3) / 4;
        const int blocks = (warps + 7) / 8;
        edge_kernel_flat<<<blocks, 256>>>(row, col, W2, b2, out, E);
    }
}

// round 11
// speedup vs baseline: 1.1716x; 1.0570x over previous
#include <cuda_runtime.h>
#include <cuda_fp16.h>

#define D 128
#define MAX_DRUG 10000
#define MAX_DIS  15000
#define MAX_E    1048576
#define KC 16            // k-chunk per smem stage (proj)
#define NB 640           // row buckets, 16 rows each (covers 10240 rows)
#define HB 512           // edge chunks (hist/scatter blocks)
#define SPLIT 8          // blocks per bucket in the edge kernel
#define EW 4             // warps per edge block
#define EPB (EW * 16)    // edges per edge-block iteration

// Projected embeddings in fp16 (fp32 math, rounded once).
__device__ __half g_Ah[MAX_DRUG * D];   // z_drug    @ W1[0:128]  + b1
__device__ __half g_Bh[MAX_DIS  * D];   // z_disease @ W1[128:256]
// Counting-sort scratch. g_cnt zero at load; re-zeroed by scatter each launch.
__device__ int  g_cnt[NB];
__device__ int  g_ptr[NB + 1];
__device__ int  g_blkhist[NB * HB];   // [bucket][chunk]  (scanbase-coalesced)
__device__ int  g_base[HB * NB];      // [chunk][bucket]  (scatter-coalesced)
__device__ int2 g_rec[MAX_E];         // (col | r_local<<28, eid)

// ---------------------------------------------------------------------------
// K1: fused projection GEMMs + per-chunk edge-row histograms.
// ---------------------------------------------------------------------------
__global__ __launch_bounds__(256) void proj_hist_kernel(
    const float* __restrict__ Zd, const float* __restrict__ Zs_,
    int n_drug, int n_dis,
    const float* __restrict__ W1, const float* __restrict__ b1,
    __half* __restrict__ A, __half* __restrict__ B,
    const int* __restrict__ row, int E, int tiles, int do_hist)
{
    const int t = threadIdx.x;

    if ((int)blockIdx.x >= tiles) {                 // ---- histogram blocks
        if (!do_hist) return;
        __shared__ int hc[NB];
        const int hb = blockIdx.x - tiles;
        const int cs = (E + HB - 1) / HB;
        const int e0 = hb * cs;
        const int e1 = min(e0 + cs, E);
        for (int i = t; i < NB; i += 256) hc[i] = 0;
        __syncthreads();
        for (int e = e0 + t; e < e1; e += 256)
            atomicAdd(&hc[row[e] >> 4], 1);
        __syncthreads();
        for (int i = t; i < NB; i += 256) {
            const int v = hc[i];
            g_blkhist[i * HB + hb] = v;            // transposed layout
            if (v) atomicAdd(&g_cnt[i], v);        // fire-and-forget RED
        }
        return;
    }

    // ---- projection blocks
    const int tiles_drug = (n_drug + 127) / 128;
    const float* Z;
    __half* out;
    int N, koff, addb;
    int tile = blockIdx.x;
    if (tile < tiles_drug) { Z = Zd;  out = A; N = n_drug; koff = 0;   addb = 1; }
    else { tile -= tiles_drug; Z = Zs_; out = B; N = n_dis; koff = 128; addb = 0; }
    const int r0 = tile * 128;

    __shared__ float Zt[KC][128];
    __shared__ float Wt[KC][128];

    const int tx = t & 15;
    const int ty = t >> 4;

    float acc[8][8];
#pragma unroll
    for (int i = 0; i < 8; i++)
#pragma unroll
        for (int j = 0; j < 8; j++) acc[i][j] = 0.f;

    for (int kc = 0; kc < D; kc += KC) {
        __syncthreads();
#pragma unroll
        for (int i = t; i < 512; i += 256) {
            int rr = i & 127;
            int k4 = i >> 7;
            float4 v = make_float4(0.f, 0.f, 0.f, 0.f);
            if (r0 + rr < N)
                v = *reinterpret_cast<const float4*>(
                        Z + (size_t)(r0 + rr) * D + kc + k4 * 4);
            Zt[k4 * 4 + 0][rr] = v.x;
            Zt[k4 * 4 + 1][rr] = v.y;
            Zt[k4 * 4 + 2][rr] = v.z;
            Zt[k4 * 4 + 3][rr] = v.w;
        }
#pragma unroll
        for (int i = t; i < 512; i += 256) {
            int kk = i >> 5;
            int c4 = i & 31;
            *reinterpret_cast<float4*>(&Wt[kk][c4 * 4]) =
                *reinterpret_cast<const float4*>(
                    W1 + (size_t)(koff + kc + kk) * D + c4 * 4);
        }
        __syncthreads();

#pragma unroll
        for (int kk = 0; kk < KC; kk++) {
            float af[8], bf[8];
            *reinterpret_cast<float4*>(af)     = *reinterpret_cast<float4*>(&Zt[kk][ty * 8]);
            *reinterpret_cast<float4*>(af + 4) = *reinterpret_cast<float4*>(&Zt[kk][ty * 8 + 4]);
            *reinterpret_cast<float4*>(bf)     = *reinterpret_cast<float4*>(&Wt[kk][tx * 8]);
            *reinterpret_cast<float4*>(bf + 4) = *reinterpret_cast<float4*>(&Wt[kk][tx * 8 + 4]);
#pragma unroll
            for (int i = 0; i < 8; i++)
#pragma unroll
                for (int j = 0; j < 8; j++)
                    acc[i][j] = fmaf(af[i], bf[j], acc[i][j]);
        }
    }

    float bias[8];
#pragma unroll
    for (int j = 0; j < 8; j++) bias[j] = addb ? b1[tx * 8 + j] : 0.f;

#pragma unroll
    for (int i = 0; i < 8; i++) {
        int r = r0 + ty * 8 + i;
        if (r < N) {
            __half2 h[4];
#pragma unroll
            for (int j = 0; j < 4; j++)
                h[j] = __floats2half2_rn(acc[i][2 * j]     + bias[2 * j],
                                         acc[i][2 * j + 1] + bias[2 * j + 1]);
            *reinterpret_cast<uint4*>(out + (size_t)r * D + tx * 8) =
                *reinterpret_cast<uint4*>(h);
        }
    }
}

// ---------------------------------------------------------------------------
// K2: merged bucket-prefix + chunk-base. Originals snapshotted to
// registers BEFORE the ping-pong scan mutates sA.
// ---------------------------------------------------------------------------
__global__ __launch_bounds__(256) void scanbase_kernel()
{
    const int b = blockIdx.x;
    const int t = threadIdx.x;

    __shared__ int sP[256], sT[256];
    int p = 0, tot = 0;
    for (int i = t; i < NB; i += 256) {
        const int v = g_cnt[i];
        tot += v;
        if (i < b) p += v;
    }
    sP[t] = p;
    sT[t] = tot;
    __syncthreads();
    for (int off = 128; off > 0; off >>= 1) {
        if (t < off) { sP[t] += sP[t + off]; sT[t] += sT[t + off]; }
        __syncthreads();
    }
    const int ptr_b = sP[0];
    if (t == 0) {
        g_ptr[b] = ptr_b;
        if (b == 0) g_ptr[NB] = sT[0];
    }

    __shared__ int sA[HB], sB[HB];
    const int2 v2 = *reinterpret_cast<const int2*>(&g_blkhist[b * HB + t * 2]);
    sA[t * 2]     = v2.x;
    sA[t * 2 + 1] = v2.y;
    __syncthreads();
    // Snapshot originals in scan index space BEFORE sA is mutated.
    const int v0 = sA[t];
    const int v1 = sA[t + 256];
    __syncthreads();

    int* src = sA;
    int* dst = sB;
#pragma unroll
    for (int off = 1; off < HB; off <<= 1) {
        int x0 = src[t];
        if (t >= off) x0 += src[t - off];
        int x1 = src[t + 256];
        if (t + 256 >= off) x1 += src[t + 256 - off];
        dst[t] = x0;
        dst[t + 256] = x1;
        __syncthreads();
        int* tmp = src; src = dst; dst = tmp;
    }
    g_base[t * NB + b]         = ptr_b + src[t] - v0;         // exclusive
    g_base[(t + 256) * NB + b] = ptr_b + src[t + 256] - v1;
}

// ---------------------------------------------------------------------------
// K3: scatter — 4-edge ILP, smem atomics against precomputed bases;
// re-arms g_cnt.
// ---------------------------------------------------------------------------
__global__ __launch_bounds__(256) void scatter_kernel(
    const int* __restrict__ row, const int* __restrict__ col, int E)
{
    __shared__ int soff[NB];
    const int hb = blockIdx.x;
    const int t  = threadIdx.x;
    const int cs = (E + HB - 1) / HB;
    const int e0 = hb * cs;
    const int e1 = min(e0 + cs, E);

    if (t < (NB + HB - 1) / HB) {
        const int i = hb + t * HB;
        if (i < NB) g_cnt[i] = 0;
    }

    for (int i = t; i < NB; i += 256) soff[i] = g_base[hb * NB + i];
    __syncthreads();

    int e = e0 + t;
    for (; e + 768 < e1; e += 1024) {
        const int r0v = row[e];
        const int r1v = row[e + 256];
        const int r2v = row[e + 512];
        const int r3v = row[e + 768];
        const int c0v = col[e];
        const int c1v = col[e + 256];
        const int c2v = col[e + 512];
        const int c3v = col[e + 768];
        const int p0 = atomicAdd(&soff[r0v >> 4], 1);
        const int p1 = atomicAdd(&soff[r1v >> 4], 1);
        const int p2 = atomicAdd(&soff[r2v >> 4], 1);
        const int p3 = atomicAdd(&soff[r3v >> 4], 1);
        g_rec[p0] = make_int2(c0v | ((r0v & 15) << 28), e);
        g_rec[p1] = make_int2(c1v | ((r1v & 15) << 28), e + 256);
        g_rec[p2] = make_int2(c2v | ((r2v & 15) << 28), e + 512);
        g_rec[p3] = make_int2(c3v | ((r3v & 15) << 28), e + 768);
    }
    for (; e < e1; e += 256) {
        const int r = row[e];
        const int c = col[e];
        const int p = atomicAdd(&soff[r >> 4], 1);
        g_rec[p] = make_int2(c | ((r & 15) << 28), e);
    }
}

// ---------------------------------------------------------------------------
// K4: bucketed edge compute. 128-thread blocks, SPLIT per bucket,
// 16 edges per warp-iteration. FOLD reduction: lane bits 3,2,1 consume
// the value index, so 8 sums over 16 lanes cost 8 SHFL (vs 32 butterfly)
// and land in the lane that stores them (one gathered STG, bit0-even
// lanes, duplicates in odd lanes discarded).
// ---------------------------------------------------------------------------
__global__ __launch_bounds__(128) void edge_sorted_kernel(
    const float* __restrict__ W2, const float* __restrict__ b2,
    float* __restrict__ out, int n_drug)
{
    __shared__ uint4 As4[16 * 16];

    const int t    = threadIdx.x;
    const int b    = blockIdx.x / SPLIT;
    const int part = blockIdx.x % SPLIT;

    {   // stage this bucket's 16 A rows (4KB)
        const uint4* A16 = reinterpret_cast<const uint4*>(g_Ah);
#pragma unroll
        for (int i = 0; i < 2; i++) {
            const int idx = t + i * 128;
            const int r = b * 16 + (idx >> 4);
            As4[idx] = (r < n_drug) ? A16[r * 16 + (idx & 15)]
                                    : make_uint4(0u, 0u, 0u, 0u);
        }
    }
    __syncthreads();

    const int s0  = g_ptr[b];
    const int len = g_ptr[b + 1] - s0;
    const int q0  = s0 + (int)(((long long)len * part) / SPLIT);
    const int q1  = s0 + (int)(((long long)len * (part + 1)) / SPLIT);
    if (q0 >= q1) return;

    const int lane = t & 31;
    const int wid  = t >> 5;
    const int l4   = lane & 15;      // lane within half-warp
    const int j    = l4;             // 16B chunk within a 256B row
    const int hi   = lane >> 4;      // half-warp id

    // Record loaders: lanes 0-7 -> edges base+0..7; lanes 16-23 -> base+8..15
    const bool loader  = (lane & 8) == 0;
    const int  loadoff = (lane & 7) + hi * 8;

    // Fold mapping: this lane ends up holding the sum for value index
    // vidx = b3*4 + b2*2 + b1 (bit0 is the duplicate bit).
    const int vidx   = ((l4 >> 3) & 1) * 4 + ((l4 >> 2) & 1) * 2 + ((l4 >> 1) & 1);
    const int eidsrc = vidx + hi * 16;        // lane holding our edge's record
    const bool writer = (l4 & 1) == 0;

    const float4 wa = reinterpret_cast<const float4*>(W2)[j * 2];
    const float4 wb = reinterpret_cast<const float4*>(W2)[j * 2 + 1];
    const __half2 w0  = __floats2half2_rn(wa.x, wa.y);
    const __half2 w1  = __floats2half2_rn(wa.z, wa.w);
    const __half2 w2h = __floats2half2_rn(wb.x, wb.y);
    const __half2 w3  = __floats2half2_rn(wb.z, wb.w);
    const float bias = b2[0];
    const __half2 zero = __float2half2_rn(0.f);
    const char* __restrict__ Bbytes = reinterpret_cast<const char*>(g_Bh);
    const unsigned joff = (unsigned)j * 16u;
    const unsigned full = 0xffffffffu;

    auto pair_dot = [&](const uint4& a, const uint4& bv) -> float {
        __half2 h0 = __hmax2(__hadd2(*reinterpret_cast<const __half2*>(&a.x),
                                     *reinterpret_cast<const __half2*>(&bv.x)), zero);
        __half2 h1 = __hmax2(__hadd2(*reinterpret_cast<const __half2*>(&a.y),
                                     *reinterpret_cast<const __half2*>(&bv.y)), zero);
        __half2 h2 = __hmax2(__hadd2(*reinterpret_cast<const __half2*>(&a.z),
                                     *reinterpret_cast<const __half2*>(&bv.z)), zero);
        __half2 h3 = __hmax2(__hadd2(*reinterpret_cast<const __half2*>(&a.w),
                                     *reinterpret_cast<const __half2*>(&bv.w)), zero);
        __half2 acc0 = __hfma2(h1, w1, __hmul2(h0, w0));
        __half2 acc1 = __hfma2(h3, w3, __hmul2(h2, w2h));
        float2 f0 = __half22float2(acc0);
        float2 f1 = __half22float2(acc1);
        return (f0.x + f0.y) + (f1.x + f1.y);
    };

    const bool b3 = (l4 & 8) != 0;
    const bool b2f = (l4 & 4) != 0;
    const bool b1f = (l4 & 2) != 0;

    int base = q0 + wid * 16;
    int2 rec = make_int2(0, 0);
    if (base < q1 && loader)
        rec = g_rec[min(base + loadoff, q1 - 1)];

    for (; base < q1; base += EPB) {
        const int nbase = base + EPB;
        int2 recn = make_int2(0, 0);
        if (nbase < q1 && loader)
            recn = g_rec[min(nbase + loadoff, q1 - 1)];

        const int n = min(16, q1 - base);

        // Pair p: low half uses record in lane p (edge p), high half uses
        // lane 16+p (edge 8+p).
        int rx[8];
#pragma unroll
        for (int p = 0; p < 8; p++)
            rx[p] = __shfl_sync(full, rec.x, p + hi * 16);

        // Front-batched B gathers: 8 independent LDG.128 in flight.
        uint4 bv[8];
#pragma unroll
        for (int p = 0; p < 8; p++) {
            const unsigned c = (unsigned)(rx[p] & 0x0FFFFFFF);
            bv[p] = *reinterpret_cast<const uint4*>(Bbytes + c * 256u + joff);
        }

        float s[8];
#pragma unroll
        for (int p = 0; p < 8; p++) {
            const int rl = ((unsigned)rx[p]) >> 28;
            s[p] = pair_dot(As4[rl * 16 + j], bv[p]);
        }

        // Fold reduction: 8 SHFL total.
        float tq[4];
#pragma unroll
        for (int q = 0; q < 4; q++) {
            float keep  = b3 ? s[q + 4] : s[q];
            float other = b3 ? s[q] : s[q + 4];
            tq[q] = keep + __shfl_xor_sync(full, other, 8);
        }
        float ur[2];
#pragma unroll
        for (int r = 0; r < 2; r++) {
            float keep  = b2f ? tq[r + 2] : tq[r];
            float other = b2f ? tq[r] : tq[r + 2];
            ur[r] = keep + __shfl_xor_sync(full, other, 4);
        }
        float v;
        {
            float keep  = b1f ? ur[1] : ur[0];
            float other = b1f ? ur[0] : ur[1];
            v = keep + __shfl_xor_sync(full, other, 2);
        }
        v += __shfl_xor_sync(full, v, 1);

        // One gathered store: even-l4 lanes write their owned edge.
        const int eid = __shfl_sync(full, rec.y, eidsrc);
        if (writer && (vidx + hi * 8) < n)
            out[eid] = v + bias;

        rec = recn;
    }
}

// ---------------------------------------------------------------------------
// Fallback flat edge kernel (round-4, known-good) for odd shapes.
// ---------------------------------------------------------------------------
__global__ __launch_bounds__(256) void edge_kernel_flat(
    const int* __restrict__ row, const int* __restrict__ col,
    const float* __restrict__ W2, const float* __restrict__ b2,
    float* __restrict__ out, int E)
{
    const int lane = threadIdx.x & 31;
    const int warp = blockIdx.x * 8 + (threadIdx.x >> 5);
    const int e0 = warp * 4;
    if (e0 >= E) return;

    const float4 w2 = reinterpret_cast<const float4*>(W2)[lane];
    const float bias = b2[0];
    const int last = E - 1;

    const int r0i = row[e0];
    const int c0i = col[e0];
    const int r1i = row[min(e0 + 1, last)];
    const int c1i = col[min(e0 + 1, last)];
    const int r2i = row[min(e0 + 2, last)];
    const int c2i = col[min(e0 + 2, last)];
    const int r3i = row[min(e0 + 3, last)];
    const int c3i = col[min(e0 + 3, last)];

    const uint2* __restrict__ Ah = reinterpret_cast<const uint2*>(g_Ah);
    const uint2* __restrict__ Bh = reinterpret_cast<const uint2*>(g_Bh);
    const uint2 a0 = Ah[(size_t)r0i * 32 + lane];
    const uint2 b0 = Bh[(size_t)c0i * 32 + lane];
    const uint2 a1 = Ah[(size_t)r1i * 32 + lane];
    const uint2 b1v = Bh[(size_t)c1i * 32 + lane];
    const uint2 a2 = Ah[(size_t)r2i * 32 + lane];
    const uint2 b2v = Bh[(size_t)c2i * 32 + lane];
    const uint2 a3 = Ah[(size_t)r3i * 32 + lane];
    const uint2 b3v = Bh[(size_t)c3i * 32 + lane];

    const __half2 zero = __float2half2_rn(0.f);
    auto edge_dot = [&](uint2 a, uint2 b) -> float {
        __half2 al = *reinterpret_cast<__half2*>(&a.x);
        __half2 ah = *reinterpret_cast<__half2*>(&a.y);
        __half2 bl = *reinterpret_cast<__half2*>(&b.x);
        __half2 bh = *reinterpret_cast<__half2*>(&b.y);
        __half2 h0 = __hmax2(__hadd2(al, bl), zero);
        __half2 h1 = __hmax2(__hadd2(ah, bh), zero);
        float2 f0 = __half22float2(h0);
        float2 f1 = __half22float2(h1);
        return f0.x * w2.x + f0.y * w2.y + f1.x * w2.z + f1.y * w2.w;
    };

    float s0 = edge_dot(a0, b0);
    float s1 = edge_dot(a1, b1v);
    float s2 = edge_dot(a2, b2v);
    float s3 = edge_dot(a3, b3v);

    const unsigned full = 0xffffffffu;
    const bool hi = (lane & 16) != 0;
    float va = hi ? s1 : s0;
    float oa = hi ? s0 : s1;
    va += __shfl_xor_sync(full, oa, 16);
    float vb = hi ? s3 : s2;
    float ob = hi ? s2 : s3;
    vb += __shfl_xor_sync(full, ob, 16);
#pragma unroll
    for (int off = 8; off > 0; off >>= 1) {
        va += __shfl_xor_sync(full, va, off);
        vb += __shfl_xor_sync(full, vb, off);
    }
    if (lane == 0) {
        out[e0] = va + bias;
        if (e0 + 2 < E) out[e0 + 2] = vb + bias;
    } else if (lane == 16) {
        if (e0 + 1 < E) out[e0 + 1] = va + bias;
        if (e0 + 3 < E) out[e0 + 3] = vb + bias;
    }
}

extern "C" void kernel_launch(void* const* d_in, const int* in_sizes, int n_in,
                              void* d_out, int out_size)
{
    const float* z_drug = (const float*)d_in[0];
    const float* z_dis  = (const float*)d_in[1];
    const int*   row    = (const int*)  d_in[2];
    const int*   col    = (const int*)  d_in[3];
    const float* W1     = (const float*)d_in[4];
    const float* b1     = (const float*)d_in[5];
    const float* W2     = (const float*)d_in[6];
    const float* b2     = (const float*)d_in[7];
    float* out = (float*)d_out;

    const int n_drug = in_sizes[0] / D;
    const int n_dis  = in_sizes[1] / D;
    const int E      = in_sizes[2];

    __half *dA = nullptr, *dB = nullptr;
    cudaGetSymbolAddress((void**)&dA, g_Ah);
    cudaGetSymbolAddress((void**)&dB, g_Bh);

    const int tiles = (n_drug + 127) / 128 + (n_dis + 127) / 128;
    const bool bucketed = (E <= MAX_E) && (n_drug <= NB * 16);

    if (bucketed) {
        proj_hist_kernel<<<tiles + HB, 256>>>(
            z_drug, z_dis, n_drug, n_dis, W1, b1, dA, dB, row, E, tiles, 1);
        scanbase_kernel<<<NB, 256>>>();
        scatter_kernel<<<HB, 256>>>(row, col, E);
        edge_sorted_kernel<<<NB * SPLIT, 128>>>(W2, b2, out, n_drug);
    } else {
        proj_hist_kernel<<<tiles, 256>>>(
            z_drug, z_dis, n_drug, n_dis, W1, b1, dA, dB, row, E, tiles, 0);
        const int warps  = (E + 3) / 4;
        const int blocks = (warps + 7) / 8;
        edge_kernel_flat<<<blocks, 256>>>(row, col, W2, b2, out, E);
    }
}

// round 12
// speedup vs baseline: 1.1860x; 1.0123x over previous
#include <cuda_runtime.h>
#include <cuda_fp16.h>

#define D 128
#define MAX_DRUG 10000
#define MAX_DIS  15000
#define MAX_E    1048576
#define KC 16            // k-chunk per smem stage (proj)
#define NB 640           // row buckets, 16 rows each (covers 10240 rows)
#define HB 512           // edge chunks (scatter blocks)
#define SLAB 4096        // per-bucket record capacity (mean 1678 @ E=1M)
#define SPLIT 8          // blocks per bucket in the edge kernel
#define EW 4             // warps per edge block
#define EPB (EW * 16)    // edges per edge-block iteration
#define PROJ_ROWS 64     // proj tile rows (fine-grained for wave balance)

// Projected embeddings in fp16 (fp32 math, rounded once).
__device__ __half g_Ah[MAX_DRUG * D];   // z_drug    @ W1[0:128]  + b1
__device__ __half g_Bh[MAX_DIS  * D];   // z_disease @ W1[128:256]
// Slab scatter state. g_cnt zeroed by reset_kernel at the head of every
// launch sequence (and is zero at module load).
__device__ int  g_cnt[NB];
__device__ int2 g_rec[NB * SLAB];       // (col | r_local<<28, eid), slabbed

// ---------------------------------------------------------------------------
// K0: reset bucket counters (tiny; runs before the fused kernel).
// ---------------------------------------------------------------------------
__global__ void reset_kernel()
{
    const int i = blockIdx.x * 256 + threadIdx.x;
    if (i < NB) g_cnt[i] = 0;
}

// ---------------------------------------------------------------------------
// K1: fused projection GEMMs + slab scatter.
// Blocks [0, tiles): 64x128 projection tiles (fp32 math, fp16 store).
// Blocks [tiles, tiles+HB): scatter — smem hist over a contiguous edge
// chunk, one global atomicAdd per (block,bucket) reserves a slab range,
// then bump-writes records. No scan kernel needed.
// ---------------------------------------------------------------------------
__global__ __launch_bounds__(256) void proj_scatter_kernel(
    const float* __restrict__ Zd, const float* __restrict__ Zs_,
    int n_drug, int n_dis,
    const float* __restrict__ W1, const float* __restrict__ b1,
    __half* __restrict__ A, __half* __restrict__ B,
    const int* __restrict__ row, const int* __restrict__ col,
    int E, int tiles, int do_scatter)
{
    __shared__ __align__(16) char smbuf[(KC * PROJ_ROWS + KC * 128) * 4];
    const int t = threadIdx.x;

    if ((int)blockIdx.x >= tiles) {                 // ---- scatter blocks
        if (!do_scatter) return;
        int* hc = (int*)smbuf;                      // NB ints (2.5KB)
        const int hb = blockIdx.x - tiles;
        const int cs = (E + HB - 1) / HB;
        const int e0 = hb * cs;
        const int e1 = min(e0 + cs, E);

        for (int i = t; i < NB; i += 256) hc[i] = 0;
        __syncthreads();
        for (int e = e0 + t; e < e1; e += 256)
            atomicAdd(&hc[row[e] >> 4], 1);
        __syncthreads();
        // Reserve slab ranges: hc[i] becomes this block's global base.
        for (int i = t; i < NB; i += 256) {
            const int v = hc[i];
            if (v) hc[i] = atomicAdd(&g_cnt[i], v);
        }
        __syncthreads();

        // Bump-write records (4-edge ILP).
        int e = e0 + t;
        for (; e + 768 < e1; e += 1024) {
            const int r0v = row[e];
            const int r1v = row[e + 256];
            const int r2v = row[e + 512];
            const int r3v = row[e + 768];
            const int c0v = col[e];
            const int c1v = col[e + 256];
            const int c2v = col[e + 512];
            const int c3v = col[e + 768];
            const int p0 = atomicAdd(&hc[r0v >> 4], 1);
            const int p1 = atomicAdd(&hc[r1v >> 4], 1);
            const int p2 = atomicAdd(&hc[r2v >> 4], 1);
            const int p3 = atomicAdd(&hc[r3v >> 4], 1);
            g_rec[(r0v >> 4) * SLAB + p0] = make_int2(c0v | ((r0v & 15) << 28), e);
            g_rec[(r1v >> 4) * SLAB + p1] = make_int2(c1v | ((r1v & 15) << 28), e + 256);
            g_rec[(r2v >> 4) * SLAB + p2] = make_int2(c2v | ((r2v & 15) << 28), e + 512);
            g_rec[(r3v >> 4) * SLAB + p3] = make_int2(c3v | ((r3v & 15) << 28), e + 768);
        }
        for (; e < e1; e += 256) {
            const int r = row[e];
            const int c = col[e];
            const int p = atomicAdd(&hc[r >> 4], 1);
            g_rec[(r >> 4) * SLAB + p] = make_int2(c | ((r & 15) << 28), e);
        }
        return;
    }

    // ---- projection blocks (64 rows x 128 cols per block)
    const int tiles_drug = (n_drug + PROJ_ROWS - 1) / PROJ_ROWS;
    const float* Z;
    __half* out;
    int N, koff, addb;
    int tile = blockIdx.x;
    if (tile < tiles_drug) { Z = Zd;  out = A; N = n_drug; koff = 0;   addb = 1; }
    else { tile -= tiles_drug; Z = Zs_; out = B; N = n_dis; koff = 128; addb = 0; }
    const int r0 = tile * PROJ_ROWS;

    float (*Zt)[PROJ_ROWS] = (float(*)[PROJ_ROWS])smbuf;                 // [KC][64]
    float (*Wt)[128] = (float(*)[128])(smbuf + KC * PROJ_ROWS * 4);      // [KC][128]

    const int tx = t & 15;          // col group: cols tx*8 .. tx*8+7
    const int ty = t >> 4;          // row group: rows ty*4 .. ty*4+3

    float acc[4][8];
#pragma unroll
    for (int i = 0; i < 4; i++)
#pragma unroll
        for (int j = 0; j < 8; j++) acc[i][j] = 0.f;

    for (int kc = 0; kc < D; kc += KC) {
        __syncthreads();
        // Z tile: 64 rows x 16 k = 256 float4 (one per thread), transposed.
        {
            const int rr = t & 63;
            const int k4 = t >> 6;   // 0..3
            float4 v = make_float4(0.f, 0.f, 0.f, 0.f);
            if (r0 + rr < N)
                v = *reinterpret_cast<const float4*>(
                        Z + (size_t)(r0 + rr) * D + kc + k4 * 4);
            Zt[k4 * 4 + 0][rr] = v.x;
            Zt[k4 * 4 + 1][rr] = v.y;
            Zt[k4 * 4 + 2][rr] = v.z;
            Zt[k4 * 4 + 3][rr] = v.w;
        }
        // W1 chunk: 16 k-rows x 128 cols, coalesced float4.
#pragma unroll
        for (int i = t; i < 512; i += 256) {
            const int kk = i >> 5;
            const int c4 = i & 31;
            *reinterpret_cast<float4*>(&Wt[kk][c4 * 4]) =
                *reinterpret_cast<const float4*>(
                    W1 + (size_t)(koff + kc + kk) * D + c4 * 4);
        }
        __syncthreads();

#pragma unroll
        for (int kk = 0; kk < KC; kk++) {
            float af[4], bf[8];
            *reinterpret_cast<float4*>(af)     = *reinterpret_cast<float4*>(&Zt[kk][ty * 4]);
            *reinterpret_cast<float4*>(bf)     = *reinterpret_cast<float4*>(&Wt[kk][tx * 8]);
            *reinterpret_cast<float4*>(bf + 4) = *reinterpret_cast<float4*>(&Wt[kk][tx * 8 + 4]);
#pragma unroll
            for (int i = 0; i < 4; i++)
#pragma unroll
                for (int j = 0; j < 8; j++)
                    acc[i][j] = fmaf(af[i], bf[j], acc[i][j]);
        }
    }

    float bias[8];
#pragma unroll
    for (int j = 0; j < 8; j++) bias[j] = addb ? b1[tx * 8 + j] : 0.f;

#pragma unroll
    for (int i = 0; i < 4; i++) {
        const int r = r0 + ty * 4 + i;
        if (r < N) {
            __half2 h[4];
#pragma unroll
            for (int j = 0; j < 4; j++)
                h[j] = __floats2half2_rn(acc[i][2 * j]     + bias[2 * j],
                                         acc[i][2 * j + 1] + bias[2 * j + 1]);
            *reinterpret_cast<uint4*>(out + (size_t)r * D + tx * 8) =
                *reinterpret_cast<uint4*>(h);
        }
    }
}

// ---------------------------------------------------------------------------
// K2: bucketed edge compute (unchanged fold-reduction design).
// Segments come from slabs: bucket b occupies [b*SLAB, b*SLAB + g_cnt[b]).
// ---------------------------------------------------------------------------
__global__ __launch_bounds__(128) void edge_sorted_kernel(
    const float* __restrict__ W2, const float* __restrict__ b2,
    float* __restrict__ out, int n_drug)
{
    __shared__ uint4 As4[16 * 16];

    const int t    = threadIdx.x;
    const int b    = blockIdx.x / SPLIT;
    const int part = blockIdx.x % SPLIT;

    {   // stage this bucket's 16 A rows (4KB)
        const uint4* A16 = reinterpret_cast<const uint4*>(g_Ah);
#pragma unroll
        for (int i = 0; i < 2; i++) {
            const int idx = t + i * 128;
            const int r = b * 16 + (idx >> 4);
            As4[idx] = (r < n_drug) ? A16[r * 16 + (idx & 15)]
                                    : make_uint4(0u, 0u, 0u, 0u);
        }
    }
    __syncthreads();

    const int s0  = b * SLAB;
    const int len = min(g_cnt[b], SLAB);
    const int q0  = s0 + (len * part) / SPLIT;
    const int q1  = s0 + (len * (part + 1)) / SPLIT;
    if (q0 >= q1) return;

    const int lane = t & 31;
    const int wid  = t >> 5;
    const int l4   = lane & 15;      // lane within half-warp
    const int j    = l4;             // 16B chunk within a 256B row
    const int hi   = lane >> 4;      // half-warp id

    // Record loaders: lanes 0-7 -> edges base+0..7; lanes 16-23 -> base+8..15
    const bool loader  = (lane & 8) == 0;
    const int  loadoff = (lane & 7) + hi * 8;

    // Fold mapping: this lane ends up holding the sum for value index
    // vidx = b3*4 + b2*2 + b1 (bit0 is the duplicate bit).
    const int vidx   = ((l4 >> 3) & 1) * 4 + ((l4 >> 2) & 1) * 2 + ((l4 >> 1) & 1);
    const int eidsrc = vidx + hi * 16;        // lane holding our edge's record
    const bool writer = (l4 & 1) == 0;

    const float4 wa = reinterpret_cast<const float4*>(W2)[j * 2];
    const float4 wb = reinterpret_cast<const float4*>(W2)[j * 2 + 1];
    const __half2 w0  = __floats2half2_rn(wa.x, wa.y);
    const __half2 w1  = __floats2half2_rn(wa.z, wa.w);
    const __half2 w2h = __floats2half2_rn(wb.x, wb.y);
    const __half2 w3  = __floats2half2_rn(wb.z, wb.w);
    const float bias = b2[0];
    const __half2 zero = __float2half2_rn(0.f);
    const char* __restrict__ Bbytes = reinterpret_cast<const char*>(g_Bh);
    const unsigned joff = (unsigned)j * 16u;
    const unsigned full = 0xffffffffu;

    auto pair_dot = [&](const uint4& a, const uint4& bv) -> float {
        __half2 h0 = __hmax2(__hadd2(*reinterpret_cast<const __half2*>(&a.x),
                                     *reinterpret_cast<const __half2*>(&bv.x)), zero);
        __half2 h1 = __hmax2(__hadd2(*reinterpret_cast<const __half2*>(&a.y),
                                     *reinterpret_cast<const __half2*>(&bv.y)), zero);
        __half2 h2 = __hmax2(__hadd2(*reinterpret_cast<const __half2*>(&a.z),
                                     *reinterpret_cast<const __half2*>(&bv.z)), zero);
        __half2 h3 = __hmax2(__hadd2(*reinterpret_cast<const __half2*>(&a.w),
                                     *reinterpret_cast<const __half2*>(&bv.w)), zero);
        __half2 acc0 = __hfma2(h1, w1, __hmul2(h0, w0));
        __half2 acc1 = __hfma2(h3, w3, __hmul2(h2, w2h));
        float2 f0 = __half22float2(acc0);
        float2 f1 = __half22float2(acc1);
        return (f0.x + f0.y) + (f1.x + f1.y);
    };

    const bool b3  = (l4 & 8) != 0;
    const bool b2f = (l4 & 4) != 0;
    const bool b1f = (l4 & 2) != 0;

    int base = q0 + wid * 16;
    int2 rec = make_int2(0, 0);
    if (base < q1 && loader)
        rec = g_rec[min(base + loadoff, q1 - 1)];

    for (; base < q1; base += EPB) {
        const int nbase = base + EPB;
        int2 recn = make_int2(0, 0);
        if (nbase < q1 && loader)
            recn = g_rec[min(nbase + loadoff, q1 - 1)];

        const int n = min(16, q1 - base);

        int rx[8];
#pragma unroll
        for (int p = 0; p < 8; p++)
            rx[p] = __shfl_sync(full, rec.x, p + hi * 16);

        uint4 bv[8];
#pragma unroll
        for (int p = 0; p < 8; p++) {
            const unsigned c = (unsigned)(rx[p] & 0x0FFFFFFF);
            bv[p] = *reinterpret_cast<const uint4*>(Bbytes + c * 256u + joff);
        }

        float s[8];
#pragma unroll
        for (int p = 0; p < 8; p++) {
            const int rl = ((unsigned)rx[p]) >> 28;
            s[p] = pair_dot(As4[rl * 16 + j], bv[p]);
        }

        // Fold reduction: 8 SHFL total.
        float tq[4];
#pragma unroll
        for (int q = 0; q < 4; q++) {
            float keep  = b3 ? s[q + 4] : s[q];
            float other = b3 ? s[q] : s[q + 4];
            tq[q] = keep + __shfl_xor_sync(full, other, 8);
        }
        float ur[2];
#pragma unroll
        for (int r = 0; r < 2; r++) {
            float keep  = b2f ? tq[r + 2] : tq[r];
            float other = b2f ? tq[r] : tq[r + 2];
            ur[r] = keep + __shfl_xor_sync(full, other, 4);
        }
        float v;
        {
            float keep  = b1f ? ur[1] : ur[0];
            float other = b1f ? ur[0] : ur[1];
            v = keep + __shfl_xor_sync(full, other, 2);
        }
        v += __shfl_xor_sync(full, v, 1);

        const int eid = __shfl_sync(full, rec.y, eidsrc);
        if (writer && (vidx + hi * 8) < n)
            out[eid] = v + bias;

        rec = recn;
    }
}

// ---------------------------------------------------------------------------
// Fallback flat edge kernel (round-4 design, known-good) for odd shapes.
// ---------------------------------------------------------------------------
__global__ __launch_bounds__(256) void edge_kernel_flat(
    const int* __restrict__ row, const int* __restrict__ col,
    const float* __restrict__ W2, const float* __restrict__ b2,
    float* __restrict__ out, int E)
{
    const int lane = threadIdx.x & 31;
    const int warp = blockIdx.x * 8 + (threadIdx.x >> 5);
    const int e0 = warp * 4;
    if (e0 >= E) return;

    const float4 w2 = reinterpret_cast<const float4*>(W2)[lane];
    const float bias = b2[0];
    const int last = E - 1;

    const int r0i = row[e0];
    const int c0i = col[e0];
    const int r1i = row[min(e0 + 1, last)];
    const int c1i = col[min(e0 + 1, last)];
    const int r2i = row[min(e0 + 2, last)];
    const int c2i = col[min(e0 + 2, last)];
    const int r3i = row[min(e0 + 3, last)];
    const int c3i = col[min(e0 + 3, last)];

    const uint2* __restrict__ Ah = reinterpret_cast<const uint2*>(g_Ah);
    const uint2* __restrict__ Bh = reinterpret_cast<const uint2*>(g_Bh);
    const uint2 a0 = Ah[(size_t)r0i * 32 + lane];
    const uint2 b0 = Bh[(size_t)c0i * 32 + lane];
    const uint2 a1 = Ah[(size_t)r1i * 32 + lane];
    const uint2 b1v = Bh[(size_t)c1i * 32 + lane];
    const uint2 a2 = Ah[(size_t)r2i * 32 + lane];
    const uint2 b2v = Bh[(size_t)c2i * 32 + lane];
    const uint2 a3 = Ah[(size_t)r3i * 32 + lane];
    const uint2 b3v = Bh[(size_t)c3i * 32 + lane];

    const __half2 zero = __float2half2_rn(0.f);
    auto edge_dot = [&](uint2 a, uint2 b) -> float {
        __half2 al = *reinterpret_cast<__half2*>(&a.x);
        __half2 ah = *reinterpret_cast<__half2*>(&a.y);
        __half2 bl = *reinterpret_cast<__half2*>(&b.x);
        __half2 bh = *reinterpret_cast<__half2*>(&b.y);
        __half2 h0 = __hmax2(__hadd2(al, bl), zero);
        __half2 h1 = __hmax2(__hadd2(ah, bh), zero);
        float2 f0 = __half22float2(h0);
        float2 f1 = __half22float2(h1);
        return f0.x * w2.x + f0.y * w2.y + f1.x * w2.z + f1.y * w2.w;
    };

    float s0 = edge_dot(a0, b0);
    float s1 = edge_dot(a1, b1v);
    float s2 = edge_dot(a2, b2v);
    float s3 = edge_dot(a3, b3v);

    const unsigned full = 0xffffffffu;
    const bool hi = (lane & 16) != 0;
    float va = hi ? s1 : s0;
    float oa = hi ? s0 : s1;
    va += __shfl_xor_sync(full, oa, 16);
    float vb = hi ? s3 : s2;
    float ob = hi ? s2 : s3;
    vb += __shfl_xor_sync(full, ob, 16);
#pragma unroll
    for (int off = 8; off > 0; off >>= 1) {
        va += __shfl_xor_sync(full, va, off);
        vb += __shfl_xor_sync(full, vb, off);
    }
    if (lane == 0) {
        out[e0] = va + bias;
        if (e0 + 2 < E) out[e0 + 2] = vb + bias;
    } else if (lane == 16) {
        if (e0 + 1 < E) out[e0 + 1] = va + bias;
        if (e0 + 3 < E) out[e0 + 3] = vb + bias;
    }
}

extern "C" void kernel_launch(void* const* d_in, const int* in_sizes, int n_in,
                              void* d_out, int out_size)
{
    const float* z_drug = (const float*)d_in[0];
    const float* z_dis  = (const float*)d_in[1];
    const int*   row    = (const int*)  d_in[2];
    const int*   col    = (const int*)  d_in[3];
    const float* W1     = (const float*)d_in[4];
    const float* b1     = (const float*)d_in[5];
    const float* W2     = (const float*)d_in[6];
    const float* b2     = (const float*)d_in[7];
    float* out = (float*)d_out;

    const int n_drug = in_sizes[0] / D;
    const int n_dis  = in_sizes[1] / D;
    const int E      = in_sizes[2];

    __half *dA = nullptr, *dB = nullptr;
    cudaGetSymbolAddress((void**)&dA, g_Ah);
    cudaGetSymbolAddress((void**)&dB, g_Bh);

    const int tiles = (n_drug + PROJ_ROWS - 1) / PROJ_ROWS
                    + (n_dis  + PROJ_ROWS - 1) / PROJ_ROWS;
    const bool bucketed = (E <= MAX_E) && (n_drug <= NB * 16);

    if (bucketed) {
        reset_kernel<<<(NB + 255) / 256, 256>>>();
        proj_scatter_kernel<<<tiles + HB, 256>>>(
            z_drug, z_dis, n_drug, n_dis, W1, b1, dA, dB,
            row, col, E, tiles, 1);
        edge_sorted_kernel<<<NB * SPLIT, 128>>>(W2, b2, out, n_drug);
    } else {
        proj_scatter_kernel<<<tiles, 256>>>(
            z_drug, z_dis, n_drug, n_dis, W1, b1, dA, dB,
            row, col, E, tiles, 0);
        const int warps  = (E + 3) / 4;
        const int blocks = (warps + 7) / 8;
        edge_kernel_flat<<<blocks, 256>>>(row, col, W2, b2, out, E);
    }
}

// round 13
// speedup vs baseline: 1.3972x; 1.1781x over previous
#include <cuda_runtime.h>
#include <cuda_fp16.h>

#define D 128
#define MAX_DRUG 10000
#define MAX_DIS  15000
#define MAX_E    1048576
#define KC 16            // k-chunk per smem stage (proj)
#define NB 640           // row buckets, 16 rows each (covers 10240 rows)
#define HB 512           // edge chunks (scatter blocks)
#define SLAB 4096        // per-bucket record capacity (mean 1678 @ E=1M)
#define SPLIT 4          // blocks per bucket in the edge kernel
#define EW 8             // warps per edge block
#define EPB (EW * 16)    // edges per edge-block iteration

// Projected embeddings in fp16 (fp32 math, rounded once).
__device__ __half g_Ah[MAX_DRUG * D];   // z_drug    @ W1[0:128]  + b1
__device__ __half g_Bh[MAX_DIS  * D];   // z_disease @ W1[128:256]
// Slab scatter state. g_cnt/g_done zero at module load; re-armed by the
// edge kernel's ticket protocol every launch (graph-replay safe).
__device__ int  g_cnt[NB];
__device__ int  g_done[NB];
__device__ int2 g_rec[NB * SLAB];       // (col | r_local<<28, eid), slabbed

// ---------------------------------------------------------------------------
// K1: fused projection GEMMs + slab scatter.
// Blocks [0, tiles): 128x128 projection tiles (fp32 math, fp16 store).
// Blocks [tiles, tiles+HB): scatter — smem hist over a contiguous edge
// chunk, one global atomicAdd per (block,bucket) reserves a slab range,
// then bump-writes records. Scatter blocks backfill proj wave holes.
// ---------------------------------------------------------------------------
__global__ __launch_bounds__(256) void proj_scatter_kernel(
    const float* __restrict__ Zd, const float* __restrict__ Zs_,
    int n_drug, int n_dis,
    const float* __restrict__ W1, const float* __restrict__ b1,
    __half* __restrict__ A, __half* __restrict__ B,
    const int* __restrict__ row, const int* __restrict__ col,
    int E, int tiles, int do_scatter)
{
    __shared__ __align__(16) char smbuf[2 * KC * 128 * 4];   // 16 KB
    const int t = threadIdx.x;

    if ((int)blockIdx.x >= tiles) {                 // ---- scatter blocks
        if (!do_scatter) return;
        int* hc = (int*)smbuf;                      // NB ints (2.5KB)
        const int hb = blockIdx.x - tiles;
        const int cs = (E + HB - 1) / HB;
        const int e0 = hb * cs;
        const int e1 = min(e0 + cs, E);

        for (int i = t; i < NB; i += 256) hc[i] = 0;
        __syncthreads();
        for (int e = e0 + t; e < e1; e += 256)
            atomicAdd(&hc[row[e] >> 4], 1);
        __syncthreads();
        // Reserve slab ranges: hc[i] becomes this block's global base.
        for (int i = t; i < NB; i += 256) {
            const int v = hc[i];
            if (v) hc[i] = atomicAdd(&g_cnt[i], v);
        }
        __syncthreads();

        // Bump-write records (4-edge ILP).
        int e = e0 + t;
        for (; e + 768 < e1; e += 1024) {
            const int r0v = row[e];
            const int r1v = row[e + 256];
            const int r2v = row[e + 512];
            const int r3v = row[e + 768];
            const int c0v = col[e];
            const int c1v = col[e + 256];
            const int c2v = col[e + 512];
            const int c3v = col[e + 768];
            const int p0 = atomicAdd(&hc[r0v >> 4], 1);
            const int p1 = atomicAdd(&hc[r1v >> 4], 1);
            const int p2 = atomicAdd(&hc[r2v >> 4], 1);
            const int p3 = atomicAdd(&hc[r3v >> 4], 1);
            g_rec[(r0v >> 4) * SLAB + p0] = make_int2(c0v | ((r0v & 15) << 28), e);
            g_rec[(r1v >> 4) * SLAB + p1] = make_int2(c1v | ((r1v & 15) << 28), e + 256);
            g_rec[(r2v >> 4) * SLAB + p2] = make_int2(c2v | ((r2v & 15) << 28), e + 512);
            g_rec[(r3v >> 4) * SLAB + p3] = make_int2(c3v | ((r3v & 15) << 28), e + 768);
        }
        for (; e < e1; e += 256) {
            const int r = row[e];
            const int c = col[e];
            const int p = atomicAdd(&hc[r >> 4], 1);
            g_rec[(r >> 4) * SLAB + p] = make_int2(c | ((r & 15) << 28), e);
        }
        return;
    }

    // ---- projection blocks (128 rows x 128 cols, 8x8 register tile)
    const int tiles_drug = (n_drug + 127) / 128;
    const float* Z;
    __half* out;
    int N, koff, addb;
    int tile = blockIdx.x;
    if (tile < tiles_drug) { Z = Zd;  out = A; N = n_drug; koff = 0;   addb = 1; }
    else { tile -= tiles_drug; Z = Zs_; out = B; N = n_dis; koff = 128; addb = 0; }
    const int r0 = tile * 128;

    float (*Zt)[128] = (float(*)[128])smbuf;                    // [KC][128]
    float (*Wt)[128] = (float(*)[128])(smbuf + KC * 128 * 4);   // [KC][128]

    const int tx = t & 15;          // col group: cols tx*8 .. tx*8+7
    const int ty = t >> 4;          // row group: rows ty*8 .. ty*8+7

    float acc[8][8];
#pragma unroll
    for (int i = 0; i < 8; i++)
#pragma unroll
        for (int j = 0; j < 8; j++) acc[i][j] = 0.f;

    for (int kc = 0; kc < D; kc += KC) {
        __syncthreads();
        // Z tile: 128 rows x 16 k = 512 float4, transposed STS.
#pragma unroll
        for (int i = t; i < 512; i += 256) {
            const int rr = i & 127;
            const int k4 = i >> 7;
            float4 v = make_float4(0.f, 0.f, 0.f, 0.f);
            if (r0 + rr < N)
                v = *reinterpret_cast<const float4*>(
                        Z + (size_t)(r0 + rr) * D + kc + k4 * 4);
            Zt[k4 * 4 + 0][rr] = v.x;
            Zt[k4 * 4 + 1][rr] = v.y;
            Zt[k4 * 4 + 2][rr] = v.z;
            Zt[k4 * 4 + 3][rr] = v.w;
        }
        // W1 chunk: 16 k-rows x 128 cols, coalesced float4.
#pragma unroll
        for (int i = t; i < 512; i += 256) {
            const int kk = i >> 5;
            const int c4 = i & 31;
            *reinterpret_cast<float4*>(&Wt[kk][c4 * 4]) =
                *reinterpret_cast<const float4*>(
                    W1 + (size_t)(koff + kc + kk) * D + c4 * 4);
        }
        __syncthreads();

#pragma unroll
        for (int kk = 0; kk < KC; kk++) {
            float af[8], bf[8];
            *reinterpret_cast<float4*>(af)     = *reinterpret_cast<float4*>(&Zt[kk][ty * 8]);
            *reinterpret_cast<float4*>(af + 4) = *reinterpret_cast<float4*>(&Zt[kk][ty * 8 + 4]);
            *reinterpret_cast<float4*>(bf)     = *reinterpret_cast<float4*>(&Wt[kk][tx * 8]);
            *reinterpret_cast<float4*>(bf + 4) = *reinterpret_cast<float4*>(&Wt[kk][tx * 8 + 4]);
#pragma unroll
            for (int i = 0; i < 8; i++)
#pragma unroll
                for (int j = 0; j < 8; j++)
                    acc[i][j] = fmaf(af[i], bf[j], acc[i][j]);
        }
    }

    float bias[8];
#pragma unroll
    for (int j = 0; j < 8; j++) bias[j] = addb ? b1[tx * 8 + j] : 0.f;

#pragma unroll
    for (int i = 0; i < 8; i++) {
        const int r = r0 + ty * 8 + i;
        if (r < N) {
            __half2 h[4];
#pragma unroll
            for (int j = 0; j < 4; j++)
                h[j] = __floats2half2_rn(acc[i][2 * j]     + bias[2 * j],
                                         acc[i][2 * j + 1] + bias[2 * j + 1]);
            *reinterpret_cast<uint4*>(out + (size_t)r * D + tx * 8) =
                *reinterpret_cast<uint4*>(h);
        }
    }
}

// ---------------------------------------------------------------------------
// K2: bucketed edge compute (fold reduction). 256 threads (8 warps),
// SPLIT=4 blocks per bucket. Ends with a ticket protocol: the last of a
// bucket's SPLIT blocks zeroes g_cnt[b] and re-arms g_done[b], replacing
// the standalone reset kernel.
// ---------------------------------------------------------------------------
__global__ __launch_bounds__(256) void edge_sorted_kernel(
    const float* __restrict__ W2, const float* __restrict__ b2,
    float* __restrict__ out, int n_drug)
{
    __shared__ uint4 As4[16 * 16];

    const int t    = threadIdx.x;
    const int b    = blockIdx.x / SPLIT;
    const int part = blockIdx.x % SPLIT;

    {   // stage this bucket's 16 A rows (4KB), one chunk per thread
        const uint4* A16 = reinterpret_cast<const uint4*>(g_Ah);
        const int r = b * 16 + (t >> 4);
        As4[t] = (r < n_drug) ? A16[r * 16 + (t & 15)]
                              : make_uint4(0u, 0u, 0u, 0u);
    }
    __syncthreads();

    const int s0  = b * SLAB;
    const int len = min(g_cnt[b], SLAB);
    const int q0  = s0 + (len * part) / SPLIT;
    const int q1  = s0 + (len * (part + 1)) / SPLIT;

    if (q0 < q1) {
        const int lane = t & 31;
        const int wid  = t >> 5;
        const int l4   = lane & 15;      // lane within half-warp
        const int j    = l4;             // 16B chunk within a 256B row
        const int hi   = lane >> 4;      // half-warp id

        const bool loader  = (lane & 8) == 0;
        const int  loadoff = (lane & 7) + hi * 8;

        // Fold mapping: lane ends holding value index vidx = b3*4+b2*2+b1.
        const int vidx   = ((l4 >> 3) & 1) * 4 + ((l4 >> 2) & 1) * 2 + ((l4 >> 1) & 1);
        const int eidsrc = vidx + hi * 16;
        const bool writer = (l4 & 1) == 0;

        const float4 wa = reinterpret_cast<const float4*>(W2)[j * 2];
        const float4 wb = reinterpret_cast<const float4*>(W2)[j * 2 + 1];
        const __half2 w0  = __floats2half2_rn(wa.x, wa.y);
        const __half2 w1  = __floats2half2_rn(wa.z, wa.w);
        const __half2 w2h = __floats2half2_rn(wb.x, wb.y);
        const __half2 w3  = __floats2half2_rn(wb.z, wb.w);
        const float bias = b2[0];
        const __half2 zero = __float2half2_rn(0.f);
        const char* __restrict__ Bbytes = reinterpret_cast<const char*>(g_Bh);
        const unsigned joff = (unsigned)j * 16u;
        const unsigned full = 0xffffffffu;

        auto pair_dot = [&](const uint4& a, const uint4& bv) -> float {
            __half2 h0 = __hmax2(__hadd2(*reinterpret_cast<const __half2*>(&a.x),
                                         *reinterpret_cast<const __half2*>(&bv.x)), zero);
            __half2 h1 = __hmax2(__hadd2(*reinterpret_cast<const __half2*>(&a.y),
                                         *reinterpret_cast<const __half2*>(&bv.y)), zero);
            __half2 h2 = __hmax2(__hadd2(*reinterpret_cast<const __half2*>(&a.z),
                                         *reinterpret_cast<const __half2*>(&bv.z)), zero);
            __half2 h3 = __hmax2(__hadd2(*reinterpret_cast<const __half2*>(&a.w),
                                         *reinterpret_cast<const __half2*>(&bv.w)), zero);
            __half2 acc0 = __hfma2(h1, w1, __hmul2(h0, w0));
            __half2 acc1 = __hfma2(h3, w3, __hmul2(h2, w2h));
            float2 f0 = __half22float2(acc0);
            float2 f1 = __half22float2(acc1);
            return (f0.x + f0.y) + (f1.x + f1.y);
        };

        const bool b3  = (l4 & 8) != 0;
        const bool b2f = (l4 & 4) != 0;
        const bool b1f = (l4 & 2) != 0;

        int base = q0 + wid * 16;
        int2 rec = make_int2(0, 0);
        if (base < q1 && loader)
            rec = g_rec[min(base + loadoff, q1 - 1)];

        for (; base < q1; base += EPB) {
            const int nbase = base + EPB;
            int2 recn = make_int2(0, 0);
            if (nbase < q1 && loader)
                recn = g_rec[min(nbase + loadoff, q1 - 1)];

            const int n = min(16, q1 - base);

            int rx[8];
#pragma unroll
            for (int p = 0; p < 8; p++)
                rx[p] = __shfl_sync(full, rec.x, p + hi * 16);

            uint4 bv[8];
#pragma unroll
            for (int p = 0; p < 8; p++) {
                const unsigned c = (unsigned)(rx[p] & 0x0FFFFFFF);
                bv[p] = *reinterpret_cast<const uint4*>(Bbytes + c * 256u + joff);
            }

            float s[8];
#pragma unroll
            for (int p = 0; p < 8; p++) {
                const int rl = ((unsigned)rx[p]) >> 28;
                s[p] = pair_dot(As4[rl * 16 + j], bv[p]);
            }

            // Fold reduction: 8 SHFL total.
            float tq[4];
#pragma unroll
            for (int q = 0; q < 4; q++) {
                float keep  = b3 ? s[q + 4] : s[q];
                float other = b3 ? s[q] : s[q + 4];
                tq[q] = keep + __shfl_xor_sync(full, other, 8);
            }
            float ur[2];
#pragma unroll
            for (int r = 0; r < 2; r++) {
                float keep  = b2f ? tq[r + 2] : tq[r];
                float other = b2f ? tq[r] : tq[r + 2];
                ur[r] = keep + __shfl_xor_sync(full, other, 4);
            }
            float v;
            {
                float keep  = b1f ? ur[1] : ur[0];
                float other = b1f ? ur[0] : ur[1];
                v = keep + __shfl_xor_sync(full, other, 2);
            }
            v += __shfl_xor_sync(full, v, 1);

            const int eid = __shfl_sync(full, rec.y, eidsrc);
            if (writer && (vidx + hi * 8) < n)
                out[eid] = v + bias;

            rec = recn;
        }
    }

    // Ticket protocol: all threads of this block have read g_cnt[b]
    // (barrier below), so the last finishing block may safely zero it
    // for the next graph replay.
    __syncthreads();
    if (t == 0) {
        const int old = atomicAdd(&g_done[b], 1);
        if (old == SPLIT - 1) {
            g_cnt[b] = 0;
            g_done[b] = 0;
        }
    }
}

// ---------------------------------------------------------------------------
// Fallback flat edge kernel (round-4 design, known-good) for odd shapes.
// ---------------------------------------------------------------------------
__global__ __launch_bounds__(256) void edge_kernel_flat(
    const int* __restrict__ row, const int* __restrict__ col,
    const float* __restrict__ W2, const float* __restrict__ b2,
    float* __restrict__ out, int E)
{
    const int lane = threadIdx.x & 31;
    const int warp = blockIdx.x * 8 + (threadIdx.x >> 5);
    const int e0 = warp * 4;
    if (e0 >= E) return;

    const float4 w2 = reinterpret_cast<const float4*>(W2)[lane];
    const float bias = b2[0];
    const int last = E - 1;

    const int r0i = row[e0];
    const int c0i = col[e0];
    const int r1i = row[min(e0 + 1, last)];
    const int c1i = col[min(e0 + 1, last)];
    const int r2i = row[min(e0 + 2, last)];
    const int c2i = col[min(e0 + 2, last)];
    const int r3i = row[min(e0 + 3, last)];
    const int c3i = col[min(e0 + 3, last)];

    const uint2* __restrict__ Ah = reinterpret_cast<const uint2*>(g_Ah);
    const uint2* __restrict__ Bh = reinterpret_cast<const uint2*>(g_Bh);
    const uint2 a0 = Ah[(size_t)r0i * 32 + lane];
    const uint2 b0 = Bh[(size_t)c0i * 32 + lane];
    const uint2 a1 = Ah[(size_t)r1i * 32 + lane];
    const uint2 b1v = Bh[(size_t)c1i * 32 + lane];
    const uint2 a2 = Ah[(size_t)r2i * 32 + lane];
    const uint2 b2v = Bh[(size_t)c2i * 32 + lane];
    const uint2 a3 = Ah[(size_t)r3i * 32 + lane];
    const uint2 b3v = Bh[(size_t)c3i * 32 + lane];

    const __half2 zero = __float2half2_rn(0.f);
    auto edge_dot = [&](uint2 a, uint2 b) -> float {
        __half2 al = *reinterpret_cast<__half2*>(&a.x);
        __half2 ah = *reinterpret_cast<__half2*>(&a.y);
        __half2 bl = *reinterpret_cast<__half2*>(&b.x);
        __half2 bh = *reinterpret_cast<__half2*>(&b.y);
        __half2 h0 = __hmax2(__hadd2(al, bl), zero);
        __half2 h1 = __hmax2(__hadd2(ah, bh), zero);
        float2 f0 = __half22float2(h0);
        float2 f1 = __half22float2(h1);
        return f0.x * w2.x + f0.y * w2.y + f1.x * w2.z + f1.y * w2.w;
    };

    float s0 = edge_dot(a0, b0);
    float s1 = edge_dot(a1, b1v);
    float s2 = edge_dot(a2, b2v);
    float s3 = edge_dot(a3, b3v);

    const unsigned full = 0xffffffffu;
    const bool hi = (lane & 16) != 0;
    float va = hi ? s1 : s0;
    float oa = hi ? s0 : s1;
    va += __shfl_xor_sync(full, oa, 16);
    float vb = hi ? s3 : s2;
    float ob = hi ? s2 : s3;
    vb += __shfl_xor_sync(full, ob, 16);
#pragma unroll
    for (int off = 8; off > 0; off >>= 1) {
        va += __shfl_xor_sync(full, va, off);
        vb += __shfl_xor_sync(full, vb, off);
    }
    if (lane == 0) {
        out[e0] = va + bias;
        if (e0 + 2 < E) out[e0 + 2] = vb + bias;
    } else if (lane == 16) {
        if (e0 + 1 < E) out[e0 + 1] = va + bias;
        if (e0 + 3 < E) out[e0 + 3] = vb + bias;
    }
}

extern "C" void kernel_launch(void* const* d_in, const int* in_sizes, int n_in,
                              void* d_out, int out_size)
{
    const float* z_drug = (const float*)d_in[0];
    const float* z_dis  = (const float*)d_in[1];
    const int*   row    = (const int*)  d_in[2];
    const int*   col    = (const int*)  d_in[3];
    const float* W1     = (const float*)d_in[4];
    const float* b1     = (const float*)d_in[5];
    const float* W2     = (const float*)d_in[6];
    const float* b2     = (const float*)d_in[7];
    float* out = (float*)d_out;

    const int n_drug = in_sizes[0] / D;
    const int n_dis  = in_sizes[1] / D;
    const int E      = in_sizes[2];

    __half *dA = nullptr, *dB = nullptr;
    cudaGetSymbolAddress((void**)&dA, g_Ah);
    cudaGetSymbolAddress((void**)&dB, g_Bh);

    const int tiles = (n_drug + 127) / 128 + (n_dis + 127) / 128;
    const bool bucketed = (E <= MAX_E) && (n_drug <= NB * 16);

    if (bucketed) {
        proj_scatter_kernel<<<tiles + HB, 256>>>(
            z_drug, z_dis, n_drug, n_dis, W1, b1, dA, dB,
            row, col, E, tiles, 1);
        edge_sorted_kernel<<<NB * SPLIT, 256>>>(W2, b2, out, n_drug);
    } else {
        proj_scatter_kernel<<<tiles, 256>>>(
            z_drug, z_dis, n_drug, n_dis, W1, b1, dA, dB,
            row, col, E, tiles, 0);
        const int warps  = (E + 3) / 4;
        const int blocks = (warps + 7) / 8;
        edge_kernel_flat<<<blocks, 256>>>(row, col, W2, b2, out, E);
    }
}

// round 14
// speedup vs baseline: 1.4035x; 1.0045x over previous
#include <cuda_runtime.h>
#include <cuda_fp16.h>

#define D 128
#define MAX_DRUG 10000
#define MAX_DIS  15000
#define MAX_E    1048576
#define KC 16            // k-chunk per smem stage (proj)
#define NB 640           // row buckets, 16 rows each (covers 10240 rows)
#define HB 512           // edge chunks (scatter blocks)
#define SLAB 4096        // per-bucket record capacity (mean 1678 @ E=1M)
#define SPLIT 4          // blocks per bucket in the edge kernel
#define EW 8             // warps per edge block
#define EPB (EW * 16)    // edges per edge-block iteration

// Projected embeddings in fp16 (fp32 math, rounded once).
__device__ __half g_Ah[MAX_DRUG * D];   // z_drug    @ W1[0:128]  + b1
__device__ __half g_Bh[MAX_DIS  * D];   // z_disease @ W1[128:256]
// Slab scatter state. g_cnt/g_done zero at module load; re-armed by the
// edge kernel's ticket protocol every launch (graph-replay safe).
__device__ int  g_cnt[NB];
__device__ int  g_done[NB];
__device__ int2 g_rec[NB * SLAB];       // (col | r_local<<28, eid), slabbed

// ---------------------------------------------------------------------------
// K1: fused projection GEMMs + slab scatter.
// Blocks [0, tiles): 128x128 projection tiles (fp32 math, fp16 store).
// Blocks [tiles, tiles+HB): scatter — smem hist over a contiguous edge
// chunk, one global atomicAdd per (block,bucket) reserves a slab range,
// then bump-writes records. Scatter blocks backfill proj wave holes.
// ---------------------------------------------------------------------------
__global__ __launch_bounds__(256) void proj_scatter_kernel(
    const float* __restrict__ Zd, const float* __restrict__ Zs_,
    int n_drug, int n_dis,
    const float* __restrict__ W1, const float* __restrict__ b1,
    __half* __restrict__ A, __half* __restrict__ B,
    const int* __restrict__ row, const int* __restrict__ col,
    int E, int tiles, int do_scatter)
{
    __shared__ __align__(16) char smbuf[2 * KC * 128 * 4];   // 16 KB
    const int t = threadIdx.x;

    if ((int)blockIdx.x >= tiles) {                 // ---- scatter blocks
        if (!do_scatter) return;
        int* hc = (int*)smbuf;                      // NB ints (2.5KB)
        const int hb = blockIdx.x - tiles;
        const int cs = (E + HB - 1) / HB;
        const int e0 = hb * cs;
        const int e1 = min(e0 + cs, E);

        for (int i = t; i < NB; i += 256) hc[i] = 0;
        __syncthreads();
        for (int e = e0 + t; e < e1; e += 256)
            atomicAdd(&hc[row[e] >> 4], 1);
        __syncthreads();
        // Reserve slab ranges: hc[i] becomes this block's global base.
        for (int i = t; i < NB; i += 256) {
            const int v = hc[i];
            if (v) hc[i] = atomicAdd(&g_cnt[i], v);
        }
        __syncthreads();

        // Bump-write records (4-edge ILP).
        int e = e0 + t;
        for (; e + 768 < e1; e += 1024) {
            const int r0v = row[e];
            const int r1v = row[e + 256];
            const int r2v = row[e + 512];
            const int r3v = row[e + 768];
            const int c0v = col[e];
            const int c1v = col[e + 256];
            const int c2v = col[e + 512];
            const int c3v = col[e + 768];
            const int p0 = atomicAdd(&hc[r0v >> 4], 1);
            const int p1 = atomicAdd(&hc[r1v >> 4], 1);
            const int p2 = atomicAdd(&hc[r2v >> 4], 1);
            const int p3 = atomicAdd(&hc[r3v >> 4], 1);
            g_rec[(r0v >> 4) * SLAB + p0] = make_int2(c0v | ((r0v & 15) << 28), e);
            g_rec[(r1v >> 4) * SLAB + p1] = make_int2(c1v | ((r1v & 15) << 28), e + 256);
            g_rec[(r2v >> 4) * SLAB + p2] = make_int2(c2v | ((r2v & 15) << 28), e + 512);
            g_rec[(r3v >> 4) * SLAB + p3] = make_int2(c3v | ((r3v & 15) << 28), e + 768);
        }
        for (; e < e1; e += 256) {
            const int r = row[e];
            const int c = col[e];
            const int p = atomicAdd(&hc[r >> 4], 1);
            g_rec[(r >> 4) * SLAB + p] = make_int2(c | ((r & 15) << 28), e);
        }
        return;
    }

    // ---- projection blocks (128 rows x 128 cols, 8x8 register tile)
    const int tiles_drug = (n_drug + 127) / 128;
    const float* Z;
    __half* out;
    int N, koff, addb;
    int tile = blockIdx.x;
    if (tile < tiles_drug) { Z = Zd;  out = A; N = n_drug; koff = 0;   addb = 1; }
    else { tile -= tiles_drug; Z = Zs_; out = B; N = n_dis; koff = 128; addb = 0; }
    const int r0 = tile * 128;

    float (*Zt)[128] = (float(*)[128])smbuf;                    // [KC][128]
    float (*Wt)[128] = (float(*)[128])(smbuf + KC * 128 * 4);   // [KC][128]

    const int tx = t & 15;          // col group: cols tx*8 .. tx*8+7
    const int ty = t >> 4;          // row group: rows ty*8 .. ty*8+7

    float acc[8][8];
#pragma unroll
    for (int i = 0; i < 8; i++)
#pragma unroll
        for (int j = 0; j < 8; j++) acc[i][j] = 0.f;

    for (int kc = 0; kc < D; kc += KC) {
        __syncthreads();
        // Z tile: 128 rows x 16 k = 512 float4, transposed STS.
#pragma unroll
        for (int i = t; i < 512; i += 256) {
            const int rr = i & 127;
            const int k4 = i >> 7;
            float4 v = make_float4(0.f, 0.f, 0.f, 0.f);
            if (r0 + rr < N)
                v = *reinterpret_cast<const float4*>(
                        Z + (size_t)(r0 + rr) * D + kc + k4 * 4);
            Zt[k4 * 4 + 0][rr] = v.x;
            Zt[k4 * 4 + 1][rr] = v.y;
            Zt[k4 * 4 + 2][rr] = v.z;
            Zt[k4 * 4 + 3][rr] = v.w;
        }
        // W1 chunk: 16 k-rows x 128 cols, coalesced float4.
#pragma unroll
        for (int i = t; i < 512; i += 256) {
            const int kk = i >> 5;
            const int c4 = i & 31;
            *reinterpret_cast<float4*>(&Wt[kk][c4 * 4]) =
                *reinterpret_cast<const float4*>(
                    W1 + (size_t)(koff + kc + kk) * D + c4 * 4);
        }
        __syncthreads();

#pragma unroll
        for (int kk = 0; kk < KC; kk++) {
            float af[8], bf[8];
            *reinterpret_cast<float4*>(af)     = *reinterpret_cast<float4*>(&Zt[kk][ty * 8]);
            *reinterpret_cast<float4*>(af + 4) = *reinterpret_cast<float4*>(&Zt[kk][ty * 8 + 4]);
            *reinterpret_cast<float4*>(bf)     = *reinterpret_cast<float4*>(&Wt[kk][tx * 8]);
            *reinterpret_cast<float4*>(bf + 4) = *reinterpret_cast<float4*>(&Wt[kk][tx * 8 + 4]);
#pragma unroll
            for (int i = 0; i < 8; i++)
#pragma unroll
                for (int j = 0; j < 8; j++)
                    acc[i][j] = fmaf(af[i], bf[j], acc[i][j]);
        }
    }

    float bias[8];
#pragma unroll
    for (int j = 0; j < 8; j++) bias[j] = addb ? b1[tx * 8 + j] : 0.f;

#pragma unroll
    for (int i = 0; i < 8; i++) {
        const int r = r0 + ty * 8 + i;
        if (r < N) {
            __half2 h[4];
#pragma unroll
            for (int j = 0; j < 4; j++)
                h[j] = __floats2half2_rn(acc[i][2 * j]     + bias[2 * j],
                                         acc[i][2 * j + 1] + bias[2 * j + 1]);
            *reinterpret_cast<uint4*>(out + (size_t)r * D + tx * 8) =
                *reinterpret_cast<uint4*>(h);
        }
    }
}

// ---------------------------------------------------------------------------
// K2: bucketed edge compute (fold reduction). 256 threads (8 warps),
// SPLIT=4 blocks per bucket, min 5 blocks/SM (reg ceiling 51 -> 62.5%
// occupancy for latency coverage of the 8 in-flight B gathers).
// Ends with a ticket protocol: the last of a bucket's SPLIT blocks
// zeroes g_cnt[b] and re-arms g_done[b] (replaces a reset kernel).
// ---------------------------------------------------------------------------
__global__ __launch_bounds__(256, 5) void edge_sorted_kernel(
    const float* __restrict__ W2, const float* __restrict__ b2,
    float* __restrict__ out, int n_drug)
{
    __shared__ uint4 As4[16 * 16];

    const int t    = threadIdx.x;
    const int b    = blockIdx.x / SPLIT;
    const int part = blockIdx.x % SPLIT;

    {   // stage this bucket's 16 A rows (4KB), one chunk per thread
        const uint4* A16 = reinterpret_cast<const uint4*>(g_Ah);
        const int r = b * 16 + (t >> 4);
        As4[t] = (r < n_drug) ? A16[r * 16 + (t & 15)]
                              : make_uint4(0u, 0u, 0u, 0u);
    }
    __syncthreads();

    const int s0  = b * SLAB;
    const int len = min(g_cnt[b], SLAB);
    const int q0  = s0 + (len * part) / SPLIT;
    const int q1  = s0 + (len * (part + 1)) / SPLIT;

    if (q0 < q1) {
        const int lane = t & 31;
        const int wid  = t >> 5;
        const int l4   = lane & 15;      // lane within half-warp
        const int j    = l4;             // 16B chunk within a 256B row
        const int hi   = lane >> 4;      // half-warp id

        const bool loader  = (lane & 8) == 0;
        const int  loadoff = (lane & 7) + hi * 8;

        // Fold mapping: lane ends holding value index vidx = b3*4+b2*2+b1.
        const int vidx   = ((l4 >> 3) & 1) * 4 + ((l4 >> 2) & 1) * 2 + ((l4 >> 1) & 1);
        const int eidsrc = vidx + hi * 16;
        const bool writer = (l4 & 1) == 0;

        const float4 wa = reinterpret_cast<const float4*>(W2)[j * 2];
        const float4 wb = reinterpret_cast<const float4*>(W2)[j * 2 + 1];
        const __half2 w0  = __floats2half2_rn(wa.x, wa.y);
        const __half2 w1  = __floats2half2_rn(wa.z, wa.w);
        const __half2 w2h = __floats2half2_rn(wb.x, wb.y);
        const __half2 w3  = __floats2half2_rn(wb.z, wb.w);
        const float bias = b2[0];
        const __half2 zero = __float2half2_rn(0.f);
        const char* __restrict__ Bbytes = reinterpret_cast<const char*>(g_Bh);
        const unsigned joff = (unsigned)j * 16u;
        const unsigned full = 0xffffffffu;

        auto pair_dot = [&](const uint4& a, const uint4& bv) -> float {
            __half2 h0 = __hmax2(__hadd2(*reinterpret_cast<const __half2*>(&a.x),
                                         *reinterpret_cast<const __half2*>(&bv.x)), zero);
            __half2 h1 = __hmax2(__hadd2(*reinterpret_cast<const __half2*>(&a.y),
                                         *reinterpret_cast<const __half2*>(&bv.y)), zero);
            __half2 h2 = __hmax2(__hadd2(*reinterpret_cast<const __half2*>(&a.z),
                                         *reinterpret_cast<const __half2*>(&bv.z)), zero);
            __half2 h3 = __hmax2(__hadd2(*reinterpret_cast<const __half2*>(&a.w),
                                         *reinterpret_cast<const __half2*>(&bv.w)), zero);
            __half2 acc0 = __hfma2(h1, w1, __hmul2(h0, w0));
            __half2 acc1 = __hfma2(h3, w3, __hmul2(h2, w2h));
            float2 f0 = __half22float2(acc0);
            float2 f1 = __half22float2(acc1);
            return (f0.x + f0.y) + (f1.x + f1.y);
        };

        const bool b3  = (l4 & 8) != 0;
        const bool b2f = (l4 & 4) != 0;
        const bool b1f = (l4 & 2) != 0;

        int base = q0 + wid * 16;
        int2 rec = make_int2(0, 0);
        if (base < q1 && loader)
            rec = g_rec[min(base + loadoff, q1 - 1)];

        for (; base < q1; base += EPB) {
            const int nbase = base + EPB;
            int2 recn = make_int2(0, 0);
            if (nbase < q1 && loader)
                recn = g_rec[min(nbase + loadoff, q1 - 1)];

            const int n = min(16, q1 - base);

            int rx[8];
#pragma unroll
            for (int p = 0; p < 8; p++)
                rx[p] = __shfl_sync(full, rec.x, p + hi * 16);

            uint4 bv[8];
#pragma unroll
            for (int p = 0; p < 8; p++) {
                const unsigned c = (unsigned)(rx[p] & 0x0FFFFFFF);
                bv[p] = *reinterpret_cast<const uint4*>(Bbytes + c * 256u + joff);
            }

            float s[8];
#pragma unroll
            for (int p = 0; p < 8; p++) {
                const int rl = ((unsigned)rx[p]) >> 28;
                s[p] = pair_dot(As4[rl * 16 + j], bv[p]);
            }

            // Fold reduction: 8 SHFL total.
            float tq[4];
#pragma unroll
            for (int q = 0; q < 4; q++) {
                float keep  = b3 ? s[q + 4] : s[q];
                float other = b3 ? s[q] : s[q + 4];
                tq[q] = keep + __shfl_xor_sync(full, other, 8);
            }
            float ur[2];
#pragma unroll
            for (int r = 0; r < 2; r++) {
                float keep  = b2f ? tq[r + 2] : tq[r];
                float other = b2f ? tq[r] : tq[r + 2];
                ur[r] = keep + __shfl_xor_sync(full, other, 4);
            }
            float v;
            {
                float keep  = b1f ? ur[1] : ur[0];
                float other = b1f ? ur[0] : ur[1];
                v = keep + __shfl_xor_sync(full, other, 2);
            }
            v += __shfl_xor_sync(full, v, 1);

            const int eid = __shfl_sync(full, rec.y, eidsrc);
            if (writer && (vidx + hi * 8) < n)
                out[eid] = v + bias;

            rec = recn;
        }
    }

    // Ticket protocol: all threads of this block have read g_cnt[b]
    // (barrier below), so the last finishing block may safely zero it
    // for the next graph replay.
    __syncthreads();
    if (t == 0) {
        const int old = atomicAdd(&g_done[b], 1);
        if (old == SPLIT - 1) {
            g_cnt[b] = 0;
            g_done[b] = 0;
        }
    }
}

// ---------------------------------------------------------------------------
// Fallback flat edge kernel (round-4 design, known-good) for odd shapes.
// ---------------------------------------------------------------------------
__global__ __launch_bounds__(256) void edge_kernel_flat(
    const int* __restrict__ row, const int* __restrict__ col,
    const float* __restrict__ W2, const float* __restrict__ b2,
    float* __restrict__ out, int E)
{
    const int lane = threadIdx.x & 31;
    const int warp = blockIdx.x * 8 + (threadIdx.x >> 5);
    const int e0 = warp * 4;
    if (e0 >= E) return;

    const float4 w2 = reinterpret_cast<const float4*>(W2)[lane];
    const float bias = b2[0];
    const int last = E - 1;

    const int r0i = row[e0];
    const int c0i = col[e0];
    const int r1i = row[min(e0 + 1, last)];
    const int c1i = col[min(e0 + 1, last)];
    const int r2i = row[min(e0 + 2, last)];
    const int c2i = col[min(e0 + 2, last)];
    const int r3i = row[min(e0 + 3, last)];
    const int c3i = col[min(e0 + 3, last)];

    const uint2* __restrict__ Ah = reinterpret_cast<const uint2*>(g_Ah);
    const uint2* __restrict__ Bh = reinterpret_cast<const uint2*>(g_Bh);
    const uint2 a0 = Ah[(size_t)r0i * 32 + lane];
    const uint2 b0 = Bh[(size_t)c0i * 32 + lane];
    const uint2 a1 = Ah[(size_t)r1i * 32 + lane];
    const uint2 b1v = Bh[(size_t)c1i * 32 + lane];
    const uint2 a2 = Ah[(size_t)r2i * 32 + lane];
    const uint2 b2v = Bh[(size_t)c2i * 32 + lane];
    const uint2 a3 = Ah[(size_t)r3i * 32 + lane];
    const uint2 b3v = Bh[(size_t)c3i * 32 + lane];

    const __half2 zero = __float2half2_rn(0.f);
    auto edge_dot = [&](uint2 a, uint2 b) -> float {
        __half2 al = *reinterpret_cast<__half2*>(&a.x);
        __half2 ah = *reinterpret_cast<__half2*>(&a.y);
        __half2 bl = *reinterpret_cast<__half2*>(&b.x);
        __half2 bh = *reinterpret_cast<__half2*>(&b.y);
        __half2 h0 = __hmax2(__hadd2(al, bl), zero);
        __half2 h1 = __hmax2(__hadd2(ah, bh), zero);
        float2 f0 = __half22float2(h0);
        float2 f1 = __half22float2(h1);
        return f0.x * w2.x + f0.y * w2.y + f1.x * w2.z + f1.y * w2.w;
    };

    float s0 = edge_dot(a0, b0);
    float s1 = edge_dot(a1, b1v);
    float s2 = edge_dot(a2, b2v);
    float s3 = edge_dot(a3, b3v);

    const unsigned full = 0xffffffffu;
    const bool hi = (lane & 16) != 0;
    float va = hi ? s1 : s0;
    float oa = hi ? s0 : s1;
    va += __shfl_xor_sync(full, oa, 16);
    float vb = hi ? s3 : s2;
    float ob = hi ? s2 : s3;
    vb += __shfl_xor_sync(full, ob, 16);
#pragma unroll
    for (int off = 8; off > 0; off >>= 1) {
        va += __shfl_xor_sync(full, va, off);
        vb += __shfl_xor_sync(full, vb, off);
    }
    if (lane == 0) {
        out[e0] = va + bias;
        if (e0 + 2 < E) out[e0 + 2] = vb + bias;
    } else if (lane == 16) {
        if (e0 + 1 < E) out[e0 + 1] = va + bias;
        if (e0 + 3 < E) out[e0 + 3] = vb + bias;
    }
}

extern "C" void kernel_launch(void* const* d_in, const int* in_sizes, int n_in,
                              void* d_out, int out_size)
{
    const float* z_drug = (const float*)d_in[0];
    const float* z_dis  = (const float*)d_in[1];
    const int*   row    = (const int*)  d_in[2];
    const int*   col    = (const int*)  d_in[3];
    const float* W1     = (const float*)d_in[4];
    const float* b1     = (const float*)d_in[5];
    const float* W2     = (const float*)d_in[6];
    const float* b2     = (const float*)d_in[7];
    float* out = (float*)d_out;

    const int n_drug = in_sizes[0] / D;
    const int n_dis  = in_sizes[1] / D;
    const int E      = in_sizes[2];

    __half *dA = nullptr, *dB = nullptr;
    cudaGetSymbolAddress((void**)&dA, g_Ah);
    cudaGetSymbolAddress((void**)&dB, g_Bh);

    const int tiles = (n_drug + 127) / 128 + (n_dis + 127) / 128;
    const bool bucketed = (E <= MAX_E) && (n_drug <= NB * 16);

    if (bucketed) {
        proj_scatter_kernel<<<tiles + HB, 256>>>(
            z_drug, z_dis, n_drug, n_dis, W1, b1, dA, dB,
            row, col, E, tiles, 1);
        edge_sorted_kernel<<<NB * SPLIT, 256>>>(W2, b2, out, n_drug);
    } else {
        proj_scatter_kernel<<<tiles, 256>>>(
            z_drug, z_dis, n_drug, n_dis, W1, b1, dA, dB,
            row, col, E, tiles, 0);
        const int warps  = (E + 3) / 4;
        const int blocks = (warps + 7) / 8;
        edge_kernel_flat<<<blocks, 256>>>(row, col, W2, b2, out, E);
    }
}